// round 12
// baseline (speedup 1.0000x reference)
#include <cuda_runtime.h>
#include <cuda_fp16.h>
#include <stdint.h>
#include <math.h>

#define R  3
#define Nn 20000
#define E  320000
#define F  256
#define H  8
#define O  64
#define D  512
#define NCHUNK 20
#define CAP 96

// ---------------- scratch (static device globals; no allocations) ----------------
__device__ __half g_a16[(size_t)R * Nn * F];
__device__ __half g_b16[(size_t)R * F * D];
__device__ __half g_w116[D * O];
__device__ __half g_h16[(size_t)R * Nn * D];
__device__ __half g_z16[(size_t)R * Nn * D];
__device__ float g_el[R * Nn * H];
__device__ float g_er[R * Nn * H];
__device__ int   g_cnt[R * Nn];
__device__ int   g_rowptr[R * (Nn + 1)];
__device__ int   g_cursor[R * Nn];
__device__ int   g_bsum[R * NCHUNK];
__device__ int   g_eid[(size_t)R * E];
__device__ float g_attn[(size_t)R * E * H];     // fallback for deg > CAP
__device__ float g_w[R * Nn];
__device__ float g_wmean[R];

union H4 {
    float2 f2;
    __half2 h2[2];
};
__device__ __forceinline__ float2 f4_to_h4(float4 v) {
    H4 u;
    u.h2[0] = __floats2half2_rn(v.x, v.y);
    u.h2[1] = __floats2half2_rn(v.z, v.w);
    return u.f2;
}

// ---------------- init: zero accumulators + fp32->fp16 conversion -----------------
#define NA4 (R * Nn * F / 4)
#define NB4 (R * F * D / 4)
#define NW4 (D * O / 4)
__global__ void k_init(const float* __restrict__ feats, const float* __restrict__ W,
                       const float* __restrict__ W1) {
    int i = blockIdx.x * blockDim.x + threadIdx.x;
    if (i < NA4)
        ((float2*)g_a16)[i] = f4_to_h4(((const float4*)feats)[i]);
    if (i < NB4)
        ((float2*)g_b16)[i] = f4_to_h4(((const float4*)W)[i]);
    if (i < NW4)
        ((float2*)g_w116)[i] = f4_to_h4(((const float4*)W1)[i]);
    if (i < R * Nn) { g_cnt[i] = 0; g_w[i] = 0.f; }
}

// ---------------- common PTX helpers ----------------------------------------------
__device__ __forceinline__ void cpa16(unsigned dst, const void* src, int bytes) {
    asm volatile("cp.async.ca.shared.global [%0], [%1], 16, %2;\n"
                 :: "r"(dst), "l"(src), "r"(bytes));
}
__device__ __forceinline__ void cpa_commit() {
    asm volatile("cp.async.commit_group;\n");
}
__device__ __forceinline__ void cpa_wait0() {
    asm volatile("cp.async.wait_group 0;\n" ::: "memory");
}
__device__ __forceinline__ void ldsm4(unsigned* r, unsigned addr) {
    asm volatile("ldmatrix.sync.aligned.m8n8.x4.shared.b16 {%0,%1,%2,%3}, [%4];"
                 : "=r"(r[0]), "=r"(r[1]), "=r"(r[2]), "=r"(r[3]) : "r"(addr));
}
__device__ __forceinline__ void ldsm4t(unsigned* r, unsigned addr) {
    asm volatile("ldmatrix.sync.aligned.m8n8.x4.trans.shared.b16 {%0,%1,%2,%3}, [%4];"
                 : "=r"(r[0]), "=r"(r[1]), "=r"(r[2]), "=r"(r[3]) : "r"(addr));
}
#define MMA16816(c4, a4, b0v, b1v) \
    asm volatile( \
        "mma.sync.aligned.m16n8k16.row.col.f32.f16.f16.f32 " \
        "{%0,%1,%2,%3}, {%4,%5,%6,%7}, {%8,%9}, {%0,%1,%2,%3};" \
        : "+f"((c4)[0]), "+f"((c4)[1]), "+f"((c4)[2]), "+f"((c4)[3]) \
        : "r"((a4)[0]), "r"((a4)[1]), "r"((a4)[2]), "r"((a4)[3]), \
          "r"(b0v), "r"(b1v))

// ================= GEMM1: 128x128x32, 4 warps (64x64), fused el/er + hist ========
#define AST2 40
#define BSTB 136
#define ASZ1 (128 * AST2)          // 5120 halves
#define BSZ1 (32 * BSTB)           // 4352 halves
#define GSM1 (2 * (ASZ1 + BSZ1) * (int)sizeof(__half))   // 37888 B

__global__ void __launch_bounds__(128) k_gemm1(
    const __half* __restrict__ A0, const __half* __restrict__ B0,
    __half* __restrict__ C16,
    const float* __restrict__ alp, const float* __restrict__ arp,
    const int* __restrict__ dstA)
{
    const int bz = blockIdx.z;
    const int tid = threadIdx.x;

    // ---- histogram blocks (overlapped with GEMM wave) ----
    if (blockIdx.y == 4u) {
        int base = blockIdx.x * 2048;
#pragma unroll
        for (int j = 0; j < 16; j++) {
            int e = base + j * 128 + tid;
            if (e < E) atomicAdd(&g_cnt[bz * Nn + dstA[(size_t)bz * E + e]], 1);
        }
        return;
    }

    extern __shared__ __half hsm[];
    __half* Asb0 = hsm;
    __half* Asb1 = hsm + ASZ1;
    __half* Bsb0 = hsm + 2 * ASZ1;
    __half* Bsb1 = hsm + 2 * ASZ1 + BSZ1;
    float* fsm = (float*)hsm;

    const __half* A = A0 + (size_t)bz * Nn * F;
    const __half* B = B0 + (size_t)bz * F * D;

    const int lane = tid & 31, wid = tid >> 5;
    const int gid  = lane >> 2, tig = lane & 3;
    const int wm   = wid >> 1, wn = wid & 1;
    const int m0   = blockIdx.x * 128, n0 = blockIdx.y * 128;

    const unsigned uA0 = (unsigned)__cvta_generic_to_shared(Asb0);
    const unsigned uA1 = (unsigned)__cvta_generic_to_shared(Asb1);
    const unsigned uB0 = (unsigned)__cvta_generic_to_shared(Bsb0);
    const unsigned uB1 = (unsigned)__cvta_generic_to_shared(Bsb1);

    // A: 4 chunks/thread, B: 4 chunks/thread (16B each)
    int aRow[4], aCh[4], aByte[4], aOK[4];
#pragma unroll
    for (int j = 0; j < 4; j++) {
        int idx = tid + j * 128;
        aRow[j] = idx >> 2;             // 0..127
        aCh[j]  = (idx & 3) * 8;        // 0,8,16,24
        aOK[j]  = (m0 + aRow[j] < Nn) ? 16 : 0;
        aByte[j] = (aRow[j] * AST2 + aCh[j]) * 2;
    }
    int bRow[4], bCh[4], bByte[4];
#pragma unroll
    for (int j = 0; j < 4; j++) {
        int idx = tid + j * 128;
        bRow[j] = idx >> 4;             // 0..31
        bCh[j]  = (idx & 15) * 8;       // 0..120
        bByte[j] = (bRow[j] * BSTB + bCh[j]) * 2;
    }

    const int aLRow = lane & 15, aLSel = lane >> 4;

    float c[4][8][4];
#pragma unroll
    for (int i = 0; i < 4; i++)
#pragma unroll
        for (int j = 0; j < 8; j++) {
            c[i][j][0] = 0.f; c[i][j][1] = 0.f;
            c[i][j][2] = 0.f; c[i][j][3] = 0.f;
        }

#pragma unroll
    for (int j = 0; j < 4; j++) {
        int gr = m0 + aRow[j];
        int grc = (gr < Nn) ? gr : 0;
        cpa16(uA0 + aByte[j], A + (size_t)grc * F + aCh[j], aOK[j]);
    }
#pragma unroll
    for (int j = 0; j < 4; j++)
        cpa16(uB0 + bByte[j], B + (size_t)bRow[j] * D + n0 + bCh[j], 16);
    cpa_commit();
    cpa_wait0();
    __syncthreads();

    const int T = F / 32;   // 8
    for (int it = 0; it < T; it++) {
        const int cur = it & 1;
        if (it + 1 < T) {
            const int k0n = (it + 1) * 32;
            const unsigned uAn = cur ? uA0 : uA1;
            const unsigned uBn = cur ? uB0 : uB1;
#pragma unroll
            for (int j = 0; j < 4; j++) {
                int gr = m0 + aRow[j];
                int grc = (gr < Nn) ? gr : 0;
                cpa16(uAn + aByte[j], A + (size_t)grc * F + k0n + aCh[j], aOK[j]);
            }
#pragma unroll
            for (int j = 0; j < 4; j++)
                cpa16(uBn + bByte[j], B + (size_t)(k0n + bRow[j]) * D + n0 + bCh[j], 16);
            cpa_commit();
        }

        const unsigned uAc = cur ? uA1 : uA0;
        const unsigned uBc = cur ? uB1 : uB0;
#pragma unroll
        for (int kg = 0; kg < 2; kg++) {
            unsigned a[4][4], b[4][4];
#pragma unroll
            for (int mt = 0; mt < 4; mt++) {
                int row = wm * 64 + mt * 16 + aLRow;
                int ch  = kg * 16 + aLSel * 8;
                ldsm4(a[mt], uAc + (unsigned)(row * AST2 + ch) * 2u);
            }
#pragma unroll
            for (int nt2 = 0; nt2 < 4; nt2++) {
                int krow = kg * 16 + aLRow;
                int ncol = wn * 64 + nt2 * 16 + aLSel * 8;
                ldsm4t(b[nt2], uBc + (unsigned)(krow * BSTB + ncol) * 2u);
            }
#pragma unroll
            for (int mt = 0; mt < 4; mt++) {
#pragma unroll
                for (int nt = 0; nt < 8; nt++) {
                    unsigned bb0 = b[nt >> 1][(nt & 1) * 2];
                    unsigned bb1 = b[nt >> 1][(nt & 1) * 2 + 1];
                    MMA16816(c[mt][nt], a[mt], bb0, bb1);
                }
            }
        }

        if (it + 1 < T) cpa_wait0();
        __syncthreads();
    }

    // ---- epilogue: h store + direct el/er (one head per warp) ----
    __half* C = C16 + (size_t)bz * Nn * D;
    fsm[tid]       = alp[bz * D + n0 + tid];
    fsm[128 + tid] = arp[bz * D + n0 + tid];
    __syncthreads();
    const int head = blockIdx.y * 2 + wn;
#pragma unroll
    for (int mt = 0; mt < 4; mt++) {
        int row = m0 + wm * 64 + mt * 16 + gid;
        float el0 = 0.f, er0 = 0.f, el1 = 0.f, er1 = 0.f;
#pragma unroll
        for (int nt = 0; nt < 8; nt++) {
            int o = wn * 64 + nt * 8 + 2 * tig;
            float al0 = fsm[o], al1 = fsm[o + 1];
            float ar0 = fsm[128 + o], ar1 = fsm[128 + o + 1];
            float v0 = c[mt][nt][0], v1 = c[mt][nt][1];
            float v2 = c[mt][nt][2], v3 = c[mt][nt][3];
            el0 = fmaf(v0, al0, fmaf(v1, al1, el0));
            er0 = fmaf(v0, ar0, fmaf(v1, ar1, er0));
            el1 = fmaf(v2, al0, fmaf(v3, al1, el1));
            er1 = fmaf(v2, ar0, fmaf(v3, ar1, er1));
            if (row < Nn)
                *(__half2*)(C + (size_t)row * D + n0 + o) = __floats2half2_rn(v0, v1);
            if (row + 8 < Nn)
                *(__half2*)(C + (size_t)(row + 8) * D + n0 + o) = __floats2half2_rn(v2, v3);
        }
#pragma unroll
        for (int off = 1; off <= 2; off <<= 1) {
            el0 += __shfl_xor_sync(0xFFFFFFFFu, el0, off);
            er0 += __shfl_xor_sync(0xFFFFFFFFu, er0, off);
            el1 += __shfl_xor_sync(0xFFFFFFFFu, el1, off);
            er1 += __shfl_xor_sync(0xFFFFFFFFu, er1, off);
        }
        if (tig == 0) {
            if (row < Nn) {
                g_el[(bz * Nn + row) * H + head] = el0;
                g_er[(bz * Nn + row) * H + head] = er0;
            }
            if (row + 8 < Nn) {
                g_el[(bz * Nn + row + 8) * H + head] = el1;
                g_er[(bz * Nn + row + 8) * H + head] = er1;
            }
        }
    }
}

// ================= GEMM2: 128x64x32, fused tanh()@W2 -> g_w =======================
#define BST2 72
#define ASZ2 (128 * AST2)
#define BSZ2 (32 * BST2)
#define GSM2 (2 * (ASZ2 + BSZ2) * (int)sizeof(__half))

__global__ void __launch_bounds__(128, 3) k_gemm2(
    const __half* __restrict__ A0, const __half* __restrict__ B0,
    const float* __restrict__ bias, const float* __restrict__ W2p)
{
    extern __shared__ __half hsm[];
    __half* Asb0 = hsm;
    __half* Asb1 = hsm + ASZ2;
    __half* Bsb0 = hsm + 2 * ASZ2;
    __half* Bsb1 = hsm + 2 * ASZ2 + BSZ2;
    float* fsm = (float*)hsm;

    const int bz = blockIdx.z;
    const int tid = threadIdx.x;
    const __half* A = A0 + (size_t)bz * Nn * D;
    const __half* B = B0;

    const int lane = tid & 31, wid = tid >> 5;
    const int gid  = lane >> 2, tig = lane & 3;
    const int wm   = wid >> 1, wn = wid & 1;
    const int m0   = blockIdx.x * 128;

    const unsigned uA0 = (unsigned)__cvta_generic_to_shared(Asb0);
    const unsigned uA1 = (unsigned)__cvta_generic_to_shared(Asb1);
    const unsigned uB0 = (unsigned)__cvta_generic_to_shared(Bsb0);
    const unsigned uB1 = (unsigned)__cvta_generic_to_shared(Bsb1);

    int aRow[4], aCh[4], aByte[4], aOK[4];
#pragma unroll
    for (int j = 0; j < 4; j++) {
        int idx = tid + j * 128;
        aRow[j] = idx >> 2;
        aCh[j]  = (idx & 3) * 8;
        aOK[j]  = (m0 + aRow[j] < Nn) ? 16 : 0;
        aByte[j] = (aRow[j] * AST2 + aCh[j]) * 2;
    }
    int bRow[2], bCh[2], bByte[2];
#pragma unroll
    for (int j = 0; j < 2; j++) {
        int idx = tid + j * 128;
        bRow[j] = idx >> 3;
        bCh[j]  = (idx & 7) * 8;
        bByte[j] = (bRow[j] * BST2 + bCh[j]) * 2;
    }
    const int aLRow = lane & 15, aLSel = lane >> 4;

    float c[4][4][4];
#pragma unroll
    for (int i = 0; i < 4; i++)
#pragma unroll
        for (int j = 0; j < 4; j++) {
            c[i][j][0] = 0.f; c[i][j][1] = 0.f;
            c[i][j][2] = 0.f; c[i][j][3] = 0.f;
        }

#pragma unroll
    for (int j = 0; j < 4; j++) {
        int gr = m0 + aRow[j];
        int grc = (gr < Nn) ? gr : 0;
        cpa16(uA0 + aByte[j], A + (size_t)grc * D + aCh[j], aOK[j]);
    }
#pragma unroll
    for (int j = 0; j < 2; j++)
        cpa16(uB0 + bByte[j], B + (size_t)bRow[j] * O + bCh[j], 16);
    cpa_commit();
    cpa_wait0();
    __syncthreads();

    const int T = D / 32;   // 16
    for (int it = 0; it < T; it++) {
        const int cur = it & 1;
        if (it + 1 < T) {
            const int k0n = (it + 1) * 32;
            const unsigned uAn = cur ? uA0 : uA1;
            const unsigned uBn = cur ? uB0 : uB1;
#pragma unroll
            for (int j = 0; j < 4; j++) {
                int gr = m0 + aRow[j];
                int grc = (gr < Nn) ? gr : 0;
                cpa16(uAn + aByte[j], A + (size_t)grc * D + k0n + aCh[j], aOK[j]);
            }
#pragma unroll
            for (int j = 0; j < 2; j++)
                cpa16(uBn + bByte[j], B + (size_t)(k0n + bRow[j]) * O + bCh[j], 16);
            cpa_commit();
        }

        const unsigned uAc = cur ? uA1 : uA0;
        const unsigned uBc = cur ? uB1 : uB0;
#pragma unroll
        for (int kg = 0; kg < 2; kg++) {
            unsigned a[4][4], b[2][4];
#pragma unroll
            for (int mt = 0; mt < 4; mt++) {
                int row = wm * 64 + mt * 16 + aLRow;
                int ch  = kg * 16 + aLSel * 8;
                ldsm4(a[mt], uAc + (unsigned)(row * AST2 + ch) * 2u);
            }
#pragma unroll
            for (int nt2 = 0; nt2 < 2; nt2++) {
                int krow = kg * 16 + aLRow;
                int ncol = wn * 32 + nt2 * 16 + aLSel * 8;
                ldsm4t(b[nt2], uBc + (unsigned)(krow * BST2 + ncol) * 2u);
            }
#pragma unroll
            for (int mt = 0; mt < 4; mt++) {
#pragma unroll
                for (int nt = 0; nt < 4; nt++) {
                    unsigned bb0 = b[nt >> 1][(nt & 1) * 2];
                    unsigned bb1 = b[nt >> 1][(nt & 1) * 2 + 1];
                    MMA16816(c[mt][nt], a[mt], bb0, bb1);
                }
            }
        }

        if (it + 1 < T) cpa_wait0();
        __syncthreads();
    }

    if (tid < 64) {
        fsm[tid]      = bias[tid];
        fsm[64 + tid] = W2p[tid];
    }
    __syncthreads();
#pragma unroll
    for (int mt = 0; mt < 4; mt++) {
        int row = m0 + wm * 64 + mt * 16 + gid;
        float w0 = 0.f, w1 = 0.f;
#pragma unroll
        for (int nt = 0; nt < 4; nt++) {
            int o = wn * 32 + nt * 8 + 2 * tig;
            float b0 = fsm[o], b1v = fsm[o + 1];
            float w2a = fsm[64 + o], w2b = fsm[64 + o + 1];
            w0 = fmaf(tanhf(c[mt][nt][0] + b0), w2a,
                 fmaf(tanhf(c[mt][nt][1] + b1v), w2b, w0));
            w1 = fmaf(tanhf(c[mt][nt][2] + b0), w2a,
                 fmaf(tanhf(c[mt][nt][3] + b1v), w2b, w1));
        }
#pragma unroll
        for (int off = 1; off <= 2; off <<= 1) {
            w0 += __shfl_xor_sync(0xFFFFFFFFu, w0, off);
            w1 += __shfl_xor_sync(0xFFFFFFFFu, w1, off);
        }
        if (tig == 0) {
            if (row < Nn)     atomicAdd(&g_w[bz * Nn + row], w0);
            if (row + 8 < Nn) atomicAdd(&g_w[bz * Nn + row + 8], w1);
        }
    }
}

// ---------------- CSR scan + scatter ----------------------------------------------
__global__ void k_scan1() {
    int chunk = blockIdx.x, r = blockIdx.y;
    int t = threadIdx.x;
    __shared__ int ws[8];
    int base = chunk * 1024 + t * 4;
    const int* cnt = g_cnt + r * Nn;
    int v[4];
#pragma unroll
    for (int j = 0; j < 4; j++) {
        int i = base + j;
        v[j] = (i < Nn) ? cnt[i] : 0;
    }
    int s = v[0] + v[1] + v[2] + v[3];
    int lane = t & 31, w = t >> 5;
    int x = s;
#pragma unroll
    for (int off = 1; off < 32; off <<= 1) {
        int y = __shfl_up_sync(0xFFFFFFFFu, x, off);
        if (lane >= off) x += y;
    }
    if (lane == 31) ws[w] = x;
    __syncthreads();
    if (t < 8) {
        int y = ws[t];
#pragma unroll
        for (int off = 1; off < 8; off <<= 1) {
            int z = __shfl_up_sync(0xFFu, y, off);
            if (t >= off) y += z;
        }
        ws[t] = y;
    }
    __syncthreads();
    int excl = x - s + (w > 0 ? ws[w - 1] : 0);
    int* rp = g_rowptr + r * (Nn + 1);
    int run = excl;
#pragma unroll
    for (int j = 0; j < 4; j++) {
        int i = base + j;
        if (i < Nn) rp[i] = run;
        run += v[j];
    }
    if (t == 255) g_bsum[r * NCHUNK + chunk] = excl + s;
}

// phase 2+3 merged: each block computes its chunk offset from g_bsum prefix
__global__ void k_scan3() {
    int chunk = blockIdx.x, r = blockIdx.y;
    int t = threadIdx.x;
    __shared__ int s_off;
    if (t == 0) {
        int acc = 0;
        for (int c = 0; c < chunk; c++) acc += g_bsum[r * NCHUNK + c];
        s_off = acc;
    }
    __syncthreads();
    int off = s_off;
    int* rp = g_rowptr + r * (Nn + 1);
#pragma unroll
    for (int j = 0; j < 4; j++) {
        int i = chunk * 1024 + t * 4 + j;
        if (i < Nn) {
            int val = rp[i] + off;
            rp[i] = val;
            g_cursor[r * Nn + i] = val;
        }
    }
    if (chunk == 0 && t == 0) rp[Nn] = E;
}

__global__ void k_scatter(const int* __restrict__ dstA) {
    int t = blockIdx.x * blockDim.x + threadIdx.x;
    if (t >= R * E) return;
    int r = t / E, e = t % E;
    int d = dstA[t];
    int p = atomicAdd(&g_cursor[r * Nn + d], 1);
    g_eid[(size_t)r * E + p] = e;
}

// ---------------- fused edge-softmax + aggregate (writes z16 only) ----------------
__global__ void __launch_bounds__(128) k_sagg(const int* __restrict__ srcA,
                                              const float* __restrict__ bias) {
    int n = blockIdx.x, r = blockIdx.y;
    int tid = threadIdx.x;
    int s0 = g_rowptr[r * (Nn + 1) + n];
    int s1 = g_rowptr[r * (Nn + 1) + n + 1];
    int deg = s1 - s0;

    __shared__ float s_attn[CAP * 8];
    __shared__ float s_m[4][8], s_s[4][8];
    __shared__ float s_M[8], s_I[8];

    const int* eid = g_eid + (size_t)r * E;
    const int* src = srcA + (size_t)r * E;
    const float* elb = g_el + (size_t)r * Nn * H;
    float* buf = (deg <= CAP) ? s_attn : (g_attn + ((size_t)r * E + s0) * H);

    int h = tid & 7, li0 = tid >> 3;
    float erv = g_er[((size_t)r * Nn + n) * H + h];
    float m = -3.4e38f, ssum = 0.f;
    for (int li = li0; li < deg; li += 16) {
        int e = eid[s0 + li];
        float v = elb[(size_t)src[e] * H + h] + erv;
        v = (v > 0.f) ? v : 0.2f * v;
        buf[li * 8 + h] = v;
        if (v > m) {
            ssum = ssum * expf(m - v) + 1.f;
            m = v;
        } else {
            ssum += expf(v - m);
        }
    }
    int lane = tid & 31, w = tid >> 5;
#pragma unroll
    for (int off = 8; off <= 16; off <<= 1) {
        float m2 = __shfl_xor_sync(0xFFFFFFFFu, m, off);
        float s2 = __shfl_xor_sync(0xFFFFFFFFu, ssum, off);
        float M = fmaxf(m, m2);
        ssum = ssum * expf(m - M) + s2 * expf(m2 - M);
        m = M;
    }
    if (lane < 8) { s_m[w][lane] = m; s_s[w][lane] = ssum; }
    __syncthreads();
    if (tid < 8) {
        float M = s_m[0][tid], S = s_s[0][tid];
#pragma unroll
        for (int ww = 1; ww < 4; ww++) {
            float m2 = s_m[ww][tid], s2 = s_s[ww][tid];
            float Mx = fmaxf(M, m2);
            S = S * expf(M - Mx) + s2 * expf(m2 - Mx);
            M = Mx;
        }
        s_M[tid] = M;
        s_I[tid] = 1.f / S;
    }
    __syncthreads();

    for (int idx = tid; idx < deg * 8; idx += 128)
        buf[idx] = expf(buf[idx] - s_M[idx & 7]) * s_I[idx & 7];
    __syncthreads();

    int col = tid * 4, hh = tid >> 4;
    const __half* hb = g_h16 + (size_t)r * Nn * D;
    float a0 = 0.f, a1 = 0.f, a2 = 0.f, a3 = 0.f;
    int li = 0;
    for (; li + 1 < deg; li += 2) {
        int e0 = eid[s0 + li], e1 = eid[s0 + li + 1];
        int sn0 = src[e0], sn1 = src[e1];
        float w0 = buf[li * 8 + hh];
        float w1 = buf[(li + 1) * 8 + hh];
        const __half2* q0 = (const __half2*)(hb + (size_t)sn0 * D + col);
        const __half2* q1 = (const __half2*)(hb + (size_t)sn1 * D + col);
        float2 u0 = __half22float2(q0[0]), u1 = __half22float2(q0[1]);
        float2 v0 = __half22float2(q1[0]), v1 = __half22float2(q1[1]);
        a0 = fmaf(w0, u0.x, a0); a1 = fmaf(w0, u0.y, a1);
        a2 = fmaf(w0, u1.x, a2); a3 = fmaf(w0, u1.y, a3);
        a0 = fmaf(w1, v0.x, a0); a1 = fmaf(w1, v0.y, a1);
        a2 = fmaf(w1, v1.x, a2); a3 = fmaf(w1, v1.y, a3);
    }
    if (li < deg) {
        int e = eid[s0 + li];
        int sn = src[e];
        float wv = buf[li * 8 + hh];
        const __half2* q = (const __half2*)(hb + (size_t)sn * D + col);
        float2 u0 = __half22float2(q[0]), u1 = __half22float2(q[1]);
        a0 = fmaf(wv, u0.x, a0); a1 = fmaf(wv, u0.y, a1);
        a2 = fmaf(wv, u1.x, a2); a3 = fmaf(wv, u1.y, a3);
    }
    float4 bv = *(const float4*)(bias + r * D + col);
    float4 o;
    o.x = fminf(fmaxf(a0 + bv.x, 0.f), 6.f);
    o.y = fminf(fmaxf(a1 + bv.y, 0.f), 6.f);
    o.z = fminf(fmaxf(a2 + bv.z, 0.f), 6.f);
    o.w = fminf(fmaxf(a3 + bv.w, 0.f), 6.f);
    *(float2*)(g_z16 + ((size_t)(r * Nn + n)) * D + col) = f4_to_h4(o);
}

// ---------------- deterministic mean over nodes -----------------------------------
__global__ void k_wreduce() {
    int r = blockIdx.x;
    __shared__ float sh[1024];
    float s = 0.f;
    for (int i = threadIdx.x; i < Nn; i += 1024) s += g_w[r * Nn + i];
    sh[threadIdx.x] = s;
    __syncthreads();
    for (int off = 512; off > 0; off >>= 1) {
        if (threadIdx.x < off) sh[threadIdx.x] += sh[threadIdx.x + off];
        __syncthreads();
    }
    if (threadIdx.x == 0) g_wmean[r] = sh[0] / (float)Nn;
}

// ---------------- out = sum_r beta[r] * z16[:, r, :] ------------------------------
__global__ void k_out(float* __restrict__ out) {
    int i = blockIdx.x * blockDim.x + threadIdx.x;
    if (i >= Nn * D / 4) return;
    float w0 = g_wmean[0], w1 = g_wmean[1], w2 = g_wmean[2];
    float mx = fmaxf(w0, fmaxf(w1, w2));
    float e0 = expf(w0 - mx), e1 = expf(w1 - mx), e2 = expf(w2 - mx);
    float inv = 1.f / (e0 + e1 + e2);
    float b0 = e0 * inv, b1 = e1 * inv, b2 = e2 * inv;
    H4 u0, u1, u2;
    u0.f2 = ((const float2*)g_z16)[i];
    u1.f2 = ((const float2*)(g_z16 + (size_t)Nn * D))[i];
    u2.f2 = ((const float2*)(g_z16 + (size_t)2 * Nn * D))[i];
    float2 p00 = __half22float2(u0.h2[0]), p01 = __half22float2(u0.h2[1]);
    float2 p10 = __half22float2(u1.h2[0]), p11 = __half22float2(u1.h2[1]);
    float2 p20 = __half22float2(u2.h2[0]), p21 = __half22float2(u2.h2[1]);
    float4 o;
    o.x = b0 * p00.x + b1 * p10.x + b2 * p20.x;
    o.y = b0 * p00.y + b1 * p10.y + b2 * p20.y;
    o.z = b0 * p01.x + b1 * p11.x + b2 * p21.x;
    o.w = b0 * p01.y + b1 * p11.y + b2 * p21.y;
    ((float4*)out)[i] = o;
}

// ---------------- host ------------------------------------------------------------
extern "C" void kernel_launch(void* const* d_in, const int* in_sizes, int n_in,
                              void* d_out, int out_size) {
    const float* feats = (const float*)d_in[0];
    const int*   src   = (const int*)d_in[1];
    const int*   dst   = (const int*)d_in[2];
    const float* W     = (const float*)d_in[3];
    const float* al    = (const float*)d_in[4];
    const float* ar    = (const float*)d_in[5];
    const float* bias  = (const float*)d_in[6];
    const float* W1    = (const float*)d_in[7];
    const float* b1    = (const float*)d_in[8];
    const float* W2    = (const float*)d_in[9];
    float* out = (float*)d_out;

    __half *aptr, *bptr, *w1ptr, *hptr, *z16ptr;
    cudaGetSymbolAddress((void**)&aptr, g_a16);
    cudaGetSymbolAddress((void**)&bptr, g_b16);
    cudaGetSymbolAddress((void**)&w1ptr, g_w116);
    cudaGetSymbolAddress((void**)&hptr, g_h16);
    cudaGetSymbolAddress((void**)&z16ptr, g_z16);

    cudaFuncSetAttribute(k_gemm1, cudaFuncAttributeMaxDynamicSharedMemorySize, GSM1);
    cudaFuncSetAttribute(k_gemm2, cudaFuncAttributeMaxDynamicSharedMemorySize, GSM2);

    k_init<<<(NA4 + 255) / 256, 256>>>(feats, W, W1);

    // GEMM1 (128x128 tiles) + overlapped histogram (blockIdx.y == 4)
    k_gemm1<<<dim3((Nn + 127) / 128, D / 128 + 1, R), 128, GSM1>>>(
        aptr, bptr, hptr, al, ar, dst);

    k_scan1<<<dim3(NCHUNK, R), 256>>>();
    k_scan3<<<dim3(NCHUNK, R), 256>>>();
    k_scatter<<<(R * E + 255) / 256, 256>>>(dst);

    k_sagg<<<dim3(Nn, R), 128>>>(src, bias);

    k_gemm2<<<dim3((Nn + 127) / 128, 1, R), 128, GSM2>>>(z16ptr, w1ptr, b1, W2);

    k_wreduce<<<R, 1024>>>();
    k_out<<<(Nn * D / 4 + 255) / 256, 256>>>(out);
}

// round 13
// speedup vs baseline: 1.3890x; 1.3890x over previous
#include <cuda_runtime.h>
#include <cuda_fp16.h>
#include <stdint.h>
#include <math.h>

#define R  3
#define Nn 20000
#define E  320000
#define F  256
#define H  8
#define O  64
#define D  512
#define NCHUNK 20
#define CAP 96

// ---------------- scratch (static device globals; no allocations) ----------------
__device__ __half g_a16[(size_t)R * Nn * F];
__device__ __half g_b16[(size_t)R * F * D];
__device__ __half g_w116[D * O];
__device__ __half g_h16[(size_t)R * Nn * D];
__device__ __half g_z16[(size_t)R * Nn * D];
__device__ float g_el[R * Nn * H];
__device__ float g_er[R * Nn * H];
__device__ int   g_cnt[R * Nn];
__device__ int   g_rowptr[R * (Nn + 1)];
__device__ int   g_cursor[R * Nn];
__device__ int   g_bsum[R * NCHUNK];
__device__ int   g_eid[(size_t)R * E];
__device__ float g_attn[(size_t)R * E * H];     // fallback for deg > CAP
__device__ float g_w[R * Nn];
__device__ float g_wmean[R];

union H4 {
    float2 f2;
    __half2 h2[2];
};
__device__ __forceinline__ float2 f4_to_h4(float4 v) {
    H4 u;
    u.h2[0] = __floats2half2_rn(v.x, v.y);
    u.h2[1] = __floats2half2_rn(v.z, v.w);
    return u.f2;
}

// ---------------- init: zero accumulators + fp32->fp16 conversion -----------------
#define NA4 (R * Nn * F / 4)
#define NB4 (R * F * D / 4)
#define NW4 (D * O / 4)
__global__ void k_init(const float* __restrict__ feats, const float* __restrict__ W,
                       const float* __restrict__ W1) {
    int i = blockIdx.x * blockDim.x + threadIdx.x;
    if (i < NA4)
        ((float2*)g_a16)[i] = f4_to_h4(((const float4*)feats)[i]);
    if (i < NB4)
        ((float2*)g_b16)[i] = f4_to_h4(((const float4*)W)[i]);
    if (i < NW4)
        ((float2*)g_w116)[i] = f4_to_h4(((const float4*)W1)[i]);
    if (i < R * Nn) { g_cnt[i] = 0; g_w[i] = 0.f; }
    if (i < R * Nn * H) { g_el[i] = 0.f; g_er[i] = 0.f; }
}

// ================= FP16 tensor-core GEMM (cp.async + ldmatrix + m16n8k16) ========
// mode 0 also hosts histogram blocks at blockIdx.y == D/GBN (overlapped with GEMM).
#define GBM 128
#define GBN 64
#define GBK 32
#define AST2 40
#define BST2 72
#define ASZ2 (GBM * AST2)
#define BSZ2 (GBK * BST2)
#define GSMEM (2 * (ASZ2 + BSZ2) * (int)sizeof(__half))

__device__ __forceinline__ void cpa16(unsigned dst, const void* src, int bytes) {
    asm volatile("cp.async.ca.shared.global [%0], [%1], 16, %2;\n"
                 :: "r"(dst), "l"(src), "r"(bytes));
}
__device__ __forceinline__ void cpa_commit() {
    asm volatile("cp.async.commit_group;\n");
}
__device__ __forceinline__ void cpa_wait0() {
    asm volatile("cp.async.wait_group 0;\n" ::: "memory");
}
__device__ __forceinline__ void ldsm4(unsigned* r, unsigned addr) {
    asm volatile("ldmatrix.sync.aligned.m8n8.x4.shared.b16 {%0,%1,%2,%3}, [%4];"
                 : "=r"(r[0]), "=r"(r[1]), "=r"(r[2]), "=r"(r[3]) : "r"(addr));
}
__device__ __forceinline__ void ldsm4t(unsigned* r, unsigned addr) {
    asm volatile("ldmatrix.sync.aligned.m8n8.x4.trans.shared.b16 {%0,%1,%2,%3}, [%4];"
                 : "=r"(r[0]), "=r"(r[1]), "=r"(r[2]), "=r"(r[3]) : "r"(addr));
}

__global__ void __launch_bounds__(128, 3) k_gemm_tc(
    const __half* __restrict__ A0, const __half* __restrict__ B0,
    __half* __restrict__ C16,
    const float* __restrict__ alp, const float* __restrict__ arp,
    const float* __restrict__ bias, const float* __restrict__ W2p,
    const int* __restrict__ dstA,
    int M, int K, int Nd,
    size_t sA, size_t sB, size_t sC, int mode)
{
    const int bz = blockIdx.z;
    const int tid = threadIdx.x;

    // ---- histogram blocks (mode 0 only, overlapped with GEMM wave) ----
    if (mode == 0 && blockIdx.y == (unsigned)(D / GBN)) {
        int base = blockIdx.x * 2048;
#pragma unroll
        for (int j = 0; j < 16; j++) {
            int e = base + j * 128 + tid;
            if (e < E) atomicAdd(&g_cnt[bz * Nn + dstA[(size_t)bz * E + e]], 1);
        }
        return;
    }

    extern __shared__ __half hsm[];
    __half* Asb0 = hsm;
    __half* Asb1 = hsm + ASZ2;
    __half* Bsb0 = hsm + 2 * ASZ2;
    __half* Bsb1 = hsm + 2 * ASZ2 + BSZ2;
    float* fsm = (float*)hsm;

    const __half* A = A0 + (size_t)bz * sA;
    const __half* B = B0 + (size_t)bz * sB;

    const int lane = tid & 31, wid = tid >> 5;
    const int gid  = lane >> 2, tig = lane & 3;
    const int wm   = wid >> 1, wn = wid & 1;
    const int m0   = blockIdx.x * GBM, n0 = blockIdx.y * GBN;

    const unsigned uA0 = (unsigned)__cvta_generic_to_shared(Asb0);
    const unsigned uA1 = (unsigned)__cvta_generic_to_shared(Asb1);
    const unsigned uB0 = (unsigned)__cvta_generic_to_shared(Bsb0);
    const unsigned uB1 = (unsigned)__cvta_generic_to_shared(Bsb1);

    int aRow[4], aCh[4], aByte[4], aOK[4];
#pragma unroll
    for (int j = 0; j < 4; j++) {
        int idx = tid + j * 128;
        aRow[j] = idx >> 2;
        aCh[j]  = (idx & 3) * 8;
        int gr = m0 + aRow[j];
        aOK[j] = (gr < M) ? 16 : 0;
        aByte[j] = (aRow[j] * AST2 + aCh[j]) * 2;
    }
    int bRow[2], bCh[2], bByte[2];
#pragma unroll
    for (int j = 0; j < 2; j++) {
        int idx = tid + j * 128;
        bRow[j] = idx >> 3;
        bCh[j]  = (idx & 7) * 8;
        bByte[j] = (bRow[j] * BST2 + bCh[j]) * 2;
    }

    const int aLRow = lane & 15, aLSel = lane >> 4;
    const int bLRow = lane & 15, bLSel = lane >> 4;

    float c[4][4][4];
#pragma unroll
    for (int i = 0; i < 4; i++)
#pragma unroll
        for (int j = 0; j < 4; j++) {
            c[i][j][0] = 0.f; c[i][j][1] = 0.f;
            c[i][j][2] = 0.f; c[i][j][3] = 0.f;
        }

#pragma unroll
    for (int j = 0; j < 4; j++) {
        int gr = m0 + aRow[j];
        int grc = (gr < M) ? gr : 0;
        cpa16(uA0 + aByte[j], A + (size_t)grc * K + aCh[j], aOK[j]);
    }
#pragma unroll
    for (int j = 0; j < 2; j++)
        cpa16(uB0 + bByte[j], B + (size_t)bRow[j] * Nd + n0 + bCh[j], 16);
    cpa_commit();
    cpa_wait0();
    __syncthreads();

    const int T = K / GBK;
    for (int it = 0; it < T; it++) {
        const int cur = it & 1;
        if (it + 1 < T) {
            const int k0n = (it + 1) * GBK;
            const unsigned uAn = cur ? uA0 : uA1;
            const unsigned uBn = cur ? uB0 : uB1;
#pragma unroll
            for (int j = 0; j < 4; j++) {
                int gr = m0 + aRow[j];
                int grc = (gr < M) ? gr : 0;
                cpa16(uAn + aByte[j], A + (size_t)grc * K + k0n + aCh[j], aOK[j]);
            }
#pragma unroll
            for (int j = 0; j < 2; j++)
                cpa16(uBn + bByte[j], B + (size_t)(k0n + bRow[j]) * Nd + n0 + bCh[j], 16);
            cpa_commit();
        }

        const unsigned uAc = cur ? uA1 : uA0;
        const unsigned uBc = cur ? uB1 : uB0;
#pragma unroll
        for (int kg = 0; kg < 2; kg++) {
            unsigned a[4][4], b[2][4];
#pragma unroll
            for (int mt = 0; mt < 4; mt++) {
                int row = wm * 64 + mt * 16 + aLRow;
                int ch  = kg * 16 + aLSel * 8;
                ldsm4(a[mt], uAc + (unsigned)(row * AST2 + ch) * 2u);
            }
#pragma unroll
            for (int nt2 = 0; nt2 < 2; nt2++) {
                int krow = kg * 16 + bLRow;
                int ncol = wn * 32 + nt2 * 16 + bLSel * 8;
                ldsm4t(b[nt2], uBc + (unsigned)(krow * BST2 + ncol) * 2u);
            }
#pragma unroll
            for (int mt = 0; mt < 4; mt++) {
#pragma unroll
                for (int nt = 0; nt < 4; nt++) {
                    unsigned bb0 = b[nt >> 1][(nt & 1) * 2];
                    unsigned bb1 = b[nt >> 1][(nt & 1) * 2 + 1];
                    asm volatile(
                        "mma.sync.aligned.m16n8k16.row.col.f32.f16.f16.f32 "
                        "{%0,%1,%2,%3}, {%4,%5,%6,%7}, {%8,%9}, {%0,%1,%2,%3};"
                        : "+f"(c[mt][nt][0]), "+f"(c[mt][nt][1]),
                          "+f"(c[mt][nt][2]), "+f"(c[mt][nt][3])
                        : "r"(a[mt][0]), "r"(a[mt][1]), "r"(a[mt][2]), "r"(a[mt][3]),
                          "r"(bb0), "r"(bb1));
                }
            }
        }

        if (it + 1 < T) cpa_wait0();
        __syncthreads();
    }

    // ---- epilogues ----
    if (mode == 0) {
        __half* C = C16 + (size_t)bz * sC;
        if (tid < 64) {
            fsm[tid]      = alp[bz * D + n0 + tid];
            fsm[64 + tid] = arp[bz * D + n0 + tid];
        }
        __syncthreads();
        const int hidx = blockIdx.y;
#pragma unroll
        for (int mt = 0; mt < 4; mt++) {
            int row = m0 + wm * 64 + mt * 16 + gid;
            float el0 = 0.f, er0 = 0.f, el1 = 0.f, er1 = 0.f;
#pragma unroll
            for (int nt = 0; nt < 4; nt++) {
                int o = wn * 32 + nt * 8 + 2 * tig;
                float al0 = fsm[o], al1 = fsm[o + 1];
                float ar0 = fsm[64 + o], ar1 = fsm[64 + o + 1];
                float v0 = c[mt][nt][0], v1 = c[mt][nt][1];
                float v2 = c[mt][nt][2], v3 = c[mt][nt][3];
                el0 = fmaf(v0, al0, fmaf(v1, al1, el0));
                er0 = fmaf(v0, ar0, fmaf(v1, ar1, er0));
                el1 = fmaf(v2, al0, fmaf(v3, al1, el1));
                er1 = fmaf(v2, ar0, fmaf(v3, ar1, er1));
                if (row < M)
                    *(__half2*)(C + (size_t)row * Nd + n0 + o) = __floats2half2_rn(v0, v1);
                if (row + 8 < M)
                    *(__half2*)(C + (size_t)(row + 8) * Nd + n0 + o) = __floats2half2_rn(v2, v3);
            }
#pragma unroll
            for (int off = 1; off <= 2; off <<= 1) {
                el0 += __shfl_xor_sync(0xFFFFFFFFu, el0, off);
                er0 += __shfl_xor_sync(0xFFFFFFFFu, er0, off);
                el1 += __shfl_xor_sync(0xFFFFFFFFu, el1, off);
                er1 += __shfl_xor_sync(0xFFFFFFFFu, er1, off);
            }
            if (tig == 0) {
                if (row < M) {
                    atomicAdd(&g_el[(bz * Nn + row) * H + hidx], el0);
                    atomicAdd(&g_er[(bz * Nn + row) * H + hidx], er0);
                }
                if (row + 8 < M) {
                    atomicAdd(&g_el[(bz * Nn + row + 8) * H + hidx], el1);
                    atomicAdd(&g_er[(bz * Nn + row + 8) * H + hidx], er1);
                }
            }
        }
    } else {
        if (tid < 64) {
            fsm[tid]      = bias[tid];
            fsm[64 + tid] = W2p[tid];
        }
        __syncthreads();
#pragma unroll
        for (int mt = 0; mt < 4; mt++) {
            int row = m0 + wm * 64 + mt * 16 + gid;
            float w0 = 0.f, w1 = 0.f;
#pragma unroll
            for (int nt = 0; nt < 4; nt++) {
                int o = wn * 32 + nt * 8 + 2 * tig;
                float b0 = fsm[o], b1v = fsm[o + 1];
                float w2a = fsm[64 + o], w2b = fsm[64 + o + 1];
                w0 = fmaf(tanhf(c[mt][nt][0] + b0), w2a,
                     fmaf(tanhf(c[mt][nt][1] + b1v), w2b, w0));
                w1 = fmaf(tanhf(c[mt][nt][2] + b0), w2a,
                     fmaf(tanhf(c[mt][nt][3] + b1v), w2b, w1));
            }
#pragma unroll
            for (int off = 1; off <= 2; off <<= 1) {
                w0 += __shfl_xor_sync(0xFFFFFFFFu, w0, off);
                w1 += __shfl_xor_sync(0xFFFFFFFFu, w1, off);
            }
            if (tig == 0) {
                if (row < M)     atomicAdd(&g_w[bz * Nn + row], w0);
                if (row + 8 < M) atomicAdd(&g_w[bz * Nn + row + 8], w1);
            }
        }
    }
}

// ---------------- CSR scan + scatter ----------------------------------------------
__global__ void k_scan1() {
    int chunk = blockIdx.x, r = blockIdx.y;
    int t = threadIdx.x;
    __shared__ int ws[8];
    int base = chunk * 1024 + t * 4;
    const int* cnt = g_cnt + r * Nn;
    int v[4];
#pragma unroll
    for (int j = 0; j < 4; j++) {
        int i = base + j;
        v[j] = (i < Nn) ? cnt[i] : 0;
    }
    int s = v[0] + v[1] + v[2] + v[3];
    int lane = t & 31, w = t >> 5;
    int x = s;
#pragma unroll
    for (int off = 1; off < 32; off <<= 1) {
        int y = __shfl_up_sync(0xFFFFFFFFu, x, off);
        if (lane >= off) x += y;
    }
    if (lane == 31) ws[w] = x;
    __syncthreads();
    if (t < 8) {
        int y = ws[t];
#pragma unroll
        for (int off = 1; off < 8; off <<= 1) {
            int z = __shfl_up_sync(0xFFu, y, off);
            if (t >= off) y += z;
        }
        ws[t] = y;
    }
    __syncthreads();
    int excl = x - s + (w > 0 ? ws[w - 1] : 0);
    int* rp = g_rowptr + r * (Nn + 1);
    int run = excl;
#pragma unroll
    for (int j = 0; j < 4; j++) {
        int i = base + j;
        if (i < Nn) rp[i] = run;
        run += v[j];
    }
    if (t == 255) g_bsum[r * NCHUNK + chunk] = excl + s;
}

// merged phase 2+3: per-block prefix of chunk sums, offset-add + cursor write
__global__ void k_scan3() {
    int chunk = blockIdx.x, r = blockIdx.y;
    int t = threadIdx.x;
    __shared__ int s_off;
    if (t == 0) {
        int acc = 0;
        for (int c = 0; c < chunk; c++) acc += g_bsum[r * NCHUNK + c];
        s_off = acc;
    }
    __syncthreads();
    int off = s_off;
    int* rp = g_rowptr + r * (Nn + 1);
#pragma unroll
    for (int j = 0; j < 4; j++) {
        int i = chunk * 1024 + t * 4 + j;
        if (i < Nn) {
            int val = rp[i] + off;
            rp[i] = val;
            g_cursor[r * Nn + i] = val;
        }
    }
    if (chunk == 0 && t == 0) rp[Nn] = E;
}

__global__ void k_scatter(const int* __restrict__ dstA) {
    int t = blockIdx.x * blockDim.x + threadIdx.x;
    if (t >= R * E) return;
    int r = t / E, e = t % E;
    int d = dstA[t];
    int p = atomicAdd(&g_cursor[r * Nn + d], 1);
    g_eid[(size_t)r * E + p] = e;
}

// ---------------- fused edge-softmax + aggregate (writes z16 only) ----------------
__global__ void __launch_bounds__(128) k_sagg(const int* __restrict__ srcA,
                                              const float* __restrict__ bias) {
    int n = blockIdx.x, r = blockIdx.y;
    int tid = threadIdx.x;
    int s0 = g_rowptr[r * (Nn + 1) + n];
    int s1 = g_rowptr[r * (Nn + 1) + n + 1];
    int deg = s1 - s0;

    __shared__ float s_attn[CAP * 8];
    __shared__ float s_m[4][8], s_s[4][8];
    __shared__ float s_M[8], s_I[8];

    const int* eid = g_eid + (size_t)r * E;
    const int* src = srcA + (size_t)r * E;
    const float* elb = g_el + (size_t)r * Nn * H;
    float* buf = (deg <= CAP) ? s_attn : (g_attn + ((size_t)r * E + s0) * H);

    int h = tid & 7, li0 = tid >> 3;
    float erv = g_er[((size_t)r * Nn + n) * H + h];
    float m = -3.4e38f, ssum = 0.f;
    for (int li = li0; li < deg; li += 16) {
        int e = eid[s0 + li];
        float v = elb[(size_t)src[e] * H + h] + erv;
        v = (v > 0.f) ? v : 0.2f * v;
        buf[li * 8 + h] = v;
        if (v > m) {
            ssum = ssum * expf(m - v) + 1.f;
            m = v;
        } else {
            ssum += expf(v - m);
        }
    }
    int lane = tid & 31, w = tid >> 5;
#pragma unroll
    for (int off = 8; off <= 16; off <<= 1) {
        float m2 = __shfl_xor_sync(0xFFFFFFFFu, m, off);
        float s2 = __shfl_xor_sync(0xFFFFFFFFu, ssum, off);
        float M = fmaxf(m, m2);
        ssum = ssum * expf(m - M) + s2 * expf(m2 - M);
        m = M;
    }
    if (lane < 8) { s_m[w][lane] = m; s_s[w][lane] = ssum; }
    __syncthreads();
    if (tid < 8) {
        float M = s_m[0][tid], S = s_s[0][tid];
#pragma unroll
        for (int ww = 1; ww < 4; ww++) {
            float m2 = s_m[ww][tid], s2 = s_s[ww][tid];
            float Mx = fmaxf(M, m2);
            S = S * expf(M - Mx) + s2 * expf(m2 - Mx);
            M = Mx;
        }
        s_M[tid] = M;
        s_I[tid] = 1.f / S;
    }
    __syncthreads();

    for (int idx = tid; idx < deg * 8; idx += 128)
        buf[idx] = expf(buf[idx] - s_M[idx & 7]) * s_I[idx & 7];
    __syncthreads();

    int col = tid * 4, hh = tid >> 4;
    const __half* hb = g_h16 + (size_t)r * Nn * D;
    float a0 = 0.f, a1 = 0.f, a2 = 0.f, a3 = 0.f;
    int li = 0;
    for (; li + 1 < deg; li += 2) {
        int e0 = eid[s0 + li], e1 = eid[s0 + li + 1];
        int sn0 = src[e0], sn1 = src[e1];
        float w0 = buf[li * 8 + hh];
        float w1 = buf[(li + 1) * 8 + hh];
        const __half2* q0 = (const __half2*)(hb + (size_t)sn0 * D + col);
        const __half2* q1 = (const __half2*)(hb + (size_t)sn1 * D + col);
        float2 u0 = __half22float2(q0[0]), u1 = __half22float2(q0[1]);
        float2 v0 = __half22float2(q1[0]), v1 = __half22float2(q1[1]);
        a0 = fmaf(w0, u0.x, a0); a1 = fmaf(w0, u0.y, a1);
        a2 = fmaf(w0, u1.x, a2); a3 = fmaf(w0, u1.y, a3);
        a0 = fmaf(w1, v0.x, a0); a1 = fmaf(w1, v0.y, a1);
        a2 = fmaf(w1, v1.x, a2); a3 = fmaf(w1, v1.y, a3);
    }
    if (li < deg) {
        int e = eid[s0 + li];
        int sn = src[e];
        float wv = buf[li * 8 + hh];
        const __half2* q = (const __half2*)(hb + (size_t)sn * D + col);
        float2 u0 = __half22float2(q[0]), u1 = __half22float2(q[1]);
        a0 = fmaf(wv, u0.x, a0); a1 = fmaf(wv, u0.y, a1);
        a2 = fmaf(wv, u1.x, a2); a3 = fmaf(wv, u1.y, a3);
    }
    float4 bv = *(const float4*)(bias + r * D + col);
    float4 o;
    o.x = fminf(fmaxf(a0 + bv.x, 0.f), 6.f);
    o.y = fminf(fmaxf(a1 + bv.y, 0.f), 6.f);
    o.z = fminf(fmaxf(a2 + bv.z, 0.f), 6.f);
    o.w = fminf(fmaxf(a3 + bv.w, 0.f), 6.f);
    *(float2*)(g_z16 + ((size_t)(r * Nn + n)) * D + col) = f4_to_h4(o);
}

// ---------------- deterministic mean over nodes -----------------------------------
__global__ void k_wreduce() {
    int r = blockIdx.x;
    __shared__ float sh[1024];
    float s = 0.f;
    for (int i = threadIdx.x; i < Nn; i += 1024) s += g_w[r * Nn + i];
    sh[threadIdx.x] = s;
    __syncthreads();
    for (int off = 512; off > 0; off >>= 1) {
        if (threadIdx.x < off) sh[threadIdx.x] += sh[threadIdx.x + off];
        __syncthreads();
    }
    if (threadIdx.x == 0) g_wmean[r] = sh[0] / (float)Nn;
}

// ---------------- out = sum_r beta[r] * z16[:, r, :] ------------------------------
__global__ void k_out(float* __restrict__ out) {
    int i = blockIdx.x * blockDim.x + threadIdx.x;
    if (i >= Nn * D / 4) return;
    float w0 = g_wmean[0], w1 = g_wmean[1], w2 = g_wmean[2];
    float mx = fmaxf(w0, fmaxf(w1, w2));
    float e0 = expf(w0 - mx), e1 = expf(w1 - mx), e2 = expf(w2 - mx);
    float inv = 1.f / (e0 + e1 + e2);
    float b0 = e0 * inv, b1 = e1 * inv, b2 = e2 * inv;
    H4 u0, u1, u2;
    u0.f2 = ((const float2*)g_z16)[i];
    u1.f2 = ((const float2*)(g_z16 + (size_t)Nn * D))[i];
    u2.f2 = ((const float2*)(g_z16 + (size_t)2 * Nn * D))[i];
    float2 p00 = __half22float2(u0.h2[0]), p01 = __half22float2(u0.h2[1]);
    float2 p10 = __half22float2(u1.h2[0]), p11 = __half22float2(u1.h2[1]);
    float2 p20 = __half22float2(u2.h2[0]), p21 = __half22float2(u2.h2[1]);
    float4 o;
    o.x = b0 * p00.x + b1 * p10.x + b2 * p20.x;
    o.y = b0 * p00.y + b1 * p10.y + b2 * p20.y;
    o.z = b0 * p01.x + b1 * p11.x + b2 * p21.x;
    o.w = b0 * p01.y + b1 * p11.y + b2 * p21.y;
    ((float4*)out)[i] = o;
}

// ---------------- host ------------------------------------------------------------
extern "C" void kernel_launch(void* const* d_in, const int* in_sizes, int n_in,
                              void* d_out, int out_size) {
    const float* feats = (const float*)d_in[0];
    const int*   src   = (const int*)d_in[1];
    const int*   dst   = (const int*)d_in[2];
    const float* W     = (const float*)d_in[3];
    const float* al    = (const float*)d_in[4];
    const float* ar    = (const float*)d_in[5];
    const float* bias  = (const float*)d_in[6];
    const float* W1    = (const float*)d_in[7];
    const float* b1    = (const float*)d_in[8];
    const float* W2    = (const float*)d_in[9];
    float* out = (float*)d_out;

    __half *aptr, *bptr, *w1ptr, *hptr, *z16ptr;
    cudaGetSymbolAddress((void**)&aptr, g_a16);
    cudaGetSymbolAddress((void**)&bptr, g_b16);
    cudaGetSymbolAddress((void**)&w1ptr, g_w116);
    cudaGetSymbolAddress((void**)&hptr, g_h16);
    cudaGetSymbolAddress((void**)&z16ptr, g_z16);

    cudaFuncSetAttribute(k_gemm_tc, cudaFuncAttributeMaxDynamicSharedMemorySize,
                         GSMEM);

    k_init<<<(NA4 + 255) / 256, 256>>>(feats, W, W1);

    // GEMM1 + overlapped histogram (blockIdx.y == 8)
    k_gemm_tc<<<dim3((Nn + GBM - 1) / GBM, D / GBN + 1, R), 128, GSMEM>>>(
        aptr, bptr, hptr, al, ar, (const float*)0, (const float*)0, dst,
        Nn, F, D, (size_t)Nn * F, (size_t)F * D, (size_t)Nn * D, 0);

    k_scan1<<<dim3(NCHUNK, R), 256>>>();
    k_scan3<<<dim3(NCHUNK, R), 256>>>();
    k_scatter<<<(R * E + 255) / 256, 256>>>(dst);

    k_sagg<<<dim3(Nn, R), 128>>>(src, bias);

    // GEMM2: w += tanh(z16 @ w116 + b1) @ W2
    k_gemm_tc<<<dim3((Nn + GBM - 1) / GBM, 1, R), 128, GSMEM>>>(
        z16ptr, w1ptr, (__half*)0, (const float*)0, (const float*)0, b1, W2,
        (const int*)0, Nn, D, O, (size_t)Nn * D, 0, 0, 1);

    k_wreduce<<<R, 1024>>>();
    k_out<<<(Nn * D / 4 + 255) / 256, 256>>>(out);
}

// round 15
// speedup vs baseline: 1.4149x; 1.0186x over previous
#include <cuda_runtime.h>
#include <cuda_fp16.h>
#include <stdint.h>
#include <math.h>

#define R  3
#define Nn 20000
#define E  320000
#define F  256
#define H  8
#define O  64
#define D  512
#define NCHUNK 20
#define CAP 96

// ---------------- scratch (static device globals; no allocations) ----------------
__device__ __half g_a16[(size_t)R * Nn * F];
__device__ __half g_b16[(size_t)R * F * D];
__device__ __half g_w116[D * O];
__device__ __half g_h16[(size_t)R * Nn * D];
__device__ __half g_z16[(size_t)R * Nn * D];
__device__ float g_el[R * Nn * H];
__device__ float g_er[R * Nn * H];
__device__ int   g_cnt[R * Nn];
__device__ int   g_rowptr[R * (Nn + 1)];
__device__ int   g_cursor[R * Nn];
__device__ int   g_bsum[R * NCHUNK];
__device__ int   g_eid[(size_t)R * E];
__device__ float g_attn[(size_t)R * E * H];     // fallback for deg > CAP
__device__ float g_w[R * Nn];
__device__ float g_wmean[R];

union H4 {
    float2 f2;
    __half2 h2[2];
};
__device__ __forceinline__ float2 f4_to_h4(float4 v) {
    H4 u;
    u.h2[0] = __floats2half2_rn(v.x, v.y);
    u.h2[1] = __floats2half2_rn(v.z, v.w);
    return u.f2;
}

// ---------------- init: zero accumulators + fp32->fp16 conversion -----------------
#define NA4 (R * Nn * F / 4)
#define NB4 (R * F * D / 4)
#define NW4 (D * O / 4)
__global__ void k_init(const float* __restrict__ feats, const float* __restrict__ W,
                       const float* __restrict__ W1) {
    int i = blockIdx.x * blockDim.x + threadIdx.x;
    if (i < NA4)
        ((float2*)g_a16)[i] = f4_to_h4(((const float4*)feats)[i]);
    if (i < NB4)
        ((float2*)g_b16)[i] = f4_to_h4(((const float4*)W)[i]);
    if (i < NW4)
        ((float2*)g_w116)[i] = f4_to_h4(((const float4*)W1)[i]);
    if (i < R * Nn) { g_cnt[i] = 0; g_w[i] = 0.f; }
    if (i < R * Nn * H) { g_el[i] = 0.f; g_er[i] = 0.f; }
}

// ================= FP16 tensor-core GEMM: 3-stage cp.async ring ===================
// mode 0 also hosts histogram blocks at blockIdx.y == D/GBN (overlapped with GEMM).
#define GBM 128
#define GBN 64
#define GBK 32
#define AST2 40
#define BST2 72
#define ASZ2 (GBM * AST2)
#define BSZ2 (GBK * BST2)
#define STAGEB ((ASZ2 + BSZ2) * 2)                  // bytes per stage
#define GSMEM (3 * STAGEB)                          // 44544 B

__device__ __forceinline__ void cpa16(unsigned dst, const void* src, int bytes) {
    asm volatile("cp.async.ca.shared.global [%0], [%1], 16, %2;\n"
                 :: "r"(dst), "l"(src), "r"(bytes));
}
__device__ __forceinline__ void cpa_commit() {
    asm volatile("cp.async.commit_group;\n");
}
__device__ __forceinline__ void cpa_wait0() {
    asm volatile("cp.async.wait_group 0;\n" ::: "memory");
}
__device__ __forceinline__ void cpa_wait1() {
    asm volatile("cp.async.wait_group 1;\n" ::: "memory");
}
__device__ __forceinline__ void ldsm4(unsigned* r, unsigned addr) {
    asm volatile("ldmatrix.sync.aligned.m8n8.x4.shared.b16 {%0,%1,%2,%3}, [%4];"
                 : "=r"(r[0]), "=r"(r[1]), "=r"(r[2]), "=r"(r[3]) : "r"(addr));
}
__device__ __forceinline__ void ldsm4t(unsigned* r, unsigned addr) {
    asm volatile("ldmatrix.sync.aligned.m8n8.x4.trans.shared.b16 {%0,%1,%2,%3}, [%4];"
                 : "=r"(r[0]), "=r"(r[1]), "=r"(r[2]), "=r"(r[3]) : "r"(addr));
}

__global__ void __launch_bounds__(128, 3) k_gemm_tc(
    const __half* __restrict__ A0, const __half* __restrict__ B0,
    __half* __restrict__ C16,
    const float* __restrict__ alp, const float* __restrict__ arp,
    const float* __restrict__ bias, const float* __restrict__ W2p,
    const int* __restrict__ dstA,
    int M, int K, int Nd,
    size_t sA, size_t sB, size_t sC, int mode)
{
    const int bz = blockIdx.z;
    const int tid = threadIdx.x;

    // ---- histogram blocks (mode 0 only, overlapped with GEMM wave) ----
    if (mode == 0 && blockIdx.y == (unsigned)(D / GBN)) {
        int base = blockIdx.x * 2048;
#pragma unroll
        for (int j = 0; j < 16; j++) {
            int e = base + j * 128 + tid;
            if (e < E) atomicAdd(&g_cnt[bz * Nn + dstA[(size_t)bz * E + e]], 1);
        }
        return;
    }

    extern __shared__ __half hsm[];
    float* fsm = (float*)hsm;

    const __half* A = A0 + (size_t)bz * sA;
    const __half* B = B0 + (size_t)bz * sB;

    const int lane = tid & 31, wid = tid >> 5;
    const int gid  = lane >> 2, tig = lane & 3;
    const int wm   = wid >> 1, wn = wid & 1;
    const int m0   = blockIdx.x * GBM, n0 = blockIdx.y * GBN;

    const unsigned uS0 = (unsigned)__cvta_generic_to_shared(hsm);

    int aRow[4], aCh[4], aByte[4], aOK[4];
#pragma unroll
    for (int j = 0; j < 4; j++) {
        int idx = tid + j * 128;
        aRow[j] = idx >> 2;
        aCh[j]  = (idx & 3) * 8;
        int gr = m0 + aRow[j];
        aOK[j] = (gr < M) ? 16 : 0;
        aByte[j] = (aRow[j] * AST2 + aCh[j]) * 2;
    }
    int bRow[2], bCh[2], bByte[2];
#pragma unroll
    for (int j = 0; j < 2; j++) {
        int idx = tid + j * 128;
        bRow[j] = idx >> 3;
        bCh[j]  = (idx & 7) * 8;
        bByte[j] = (bRow[j] * BST2 + bCh[j]) * 2;
    }

    const int aLRow = lane & 15, aLSel = lane >> 4;
    const int bLRow = lane & 15, bLSel = lane >> 4;

    float c[4][4][4];
#pragma unroll
    for (int i = 0; i < 4; i++)
#pragma unroll
        for (int j = 0; j < 4; j++) {
            c[i][j][0] = 0.f; c[i][j][1] = 0.f;
            c[i][j][2] = 0.f; c[i][j][3] = 0.f;
        }

    const int T = K / GBK;

    // ---- prologue: stage 0 and stage 1 ----
#pragma unroll
    for (int st = 0; st < 2; st++) {
        if (st < T) {
            unsigned uAs = uS0 + st * STAGEB;
            unsigned uBs = uAs + ASZ2 * 2;
            int k0 = st * GBK;
#pragma unroll
            for (int j = 0; j < 4; j++) {
                int gr = m0 + aRow[j];
                int grc = (gr < M) ? gr : 0;
                cpa16(uAs + aByte[j], A + (size_t)grc * K + k0 + aCh[j], aOK[j]);
            }
#pragma unroll
            for (int j = 0; j < 2; j++)
                cpa16(uBs + bByte[j], B + (size_t)(k0 + bRow[j]) * Nd + n0 + bCh[j], 16);
            cpa_commit();
        }
    }

    for (int it = 0; it < T; it++) {
        if (it + 1 < T) cpa_wait1(); else cpa_wait0();
        __syncthreads();

        if (it + 2 < T) {
            int s2 = (it + 2) % 3;
            unsigned uAs = uS0 + s2 * STAGEB;
            unsigned uBs = uAs + ASZ2 * 2;
            int k0 = (it + 2) * GBK;
#pragma unroll
            for (int j = 0; j < 4; j++) {
                int gr = m0 + aRow[j];
                int grc = (gr < M) ? gr : 0;
                cpa16(uAs + aByte[j], A + (size_t)grc * K + k0 + aCh[j], aOK[j]);
            }
#pragma unroll
            for (int j = 0; j < 2; j++)
                cpa16(uBs + bByte[j], B + (size_t)(k0 + bRow[j]) * Nd + n0 + bCh[j], 16);
            cpa_commit();
        }

        int s = it % 3;
        unsigned uAc = uS0 + s * STAGEB;
        unsigned uBc = uAc + ASZ2 * 2;
#pragma unroll
        for (int kg = 0; kg < 2; kg++) {
            unsigned a[4][4], b[2][4];
#pragma unroll
            for (int mt = 0; mt < 4; mt++) {
                int row = wm * 64 + mt * 16 + aLRow;
                int ch  = kg * 16 + aLSel * 8;
                ldsm4(a[mt], uAc + (unsigned)(row * AST2 + ch) * 2u);
            }
#pragma unroll
            for (int nt2 = 0; nt2 < 2; nt2++) {
                int krow = kg * 16 + bLRow;
                int ncol = wn * 32 + nt2 * 16 + bLSel * 8;
                ldsm4t(b[nt2], uBc + (unsigned)(krow * BST2 + ncol) * 2u);
            }
#pragma unroll
            for (int mt = 0; mt < 4; mt++) {
#pragma unroll
                for (int nt = 0; nt < 4; nt++) {
                    unsigned bb0 = b[nt >> 1][(nt & 1) * 2];
                    unsigned bb1 = b[nt >> 1][(nt & 1) * 2 + 1];
                    asm volatile(
                        "mma.sync.aligned.m16n8k16.row.col.f32.f16.f16.f32 "
                        "{%0,%1,%2,%3}, {%4,%5,%6,%7}, {%8,%9}, {%0,%1,%2,%3};"
                        : "+f"(c[mt][nt][0]), "+f"(c[mt][nt][1]),
                          "+f"(c[mt][nt][2]), "+f"(c[mt][nt][3])
                        : "r"(a[mt][0]), "r"(a[mt][1]), "r"(a[mt][2]), "r"(a[mt][3]),
                          "r"(bb0), "r"(bb1));
                }
            }
        }
    }
    __syncthreads();   // epilogue fsm aliases stage 0 — all compute must finish

    // ---- epilogues ----
    if (mode == 0) {
        __half* C = C16 + (size_t)bz * sC;
        if (tid < 64) {
            fsm[tid]      = alp[bz * D + n0 + tid];
            fsm[64 + tid] = arp[bz * D + n0 + tid];
        }
        __syncthreads();
        const int hidx = blockIdx.y;
#pragma unroll
        for (int mt = 0; mt < 4; mt++) {
            int row = m0 + wm * 64 + mt * 16 + gid;
            float el0 = 0.f, er0 = 0.f, el1 = 0.f, er1 = 0.f;
#pragma unroll
            for (int nt = 0; nt < 4; nt++) {
                int o = wn * 32 + nt * 8 + 2 * tig;
                float al0 = fsm[o], al1 = fsm[o + 1];
                float ar0 = fsm[64 + o], ar1 = fsm[64 + o + 1];
                float v0 = c[mt][nt][0], v1 = c[mt][nt][1];
                float v2 = c[mt][nt][2], v3 = c[mt][nt][3];
                el0 = fmaf(v0, al0, fmaf(v1, al1, el0));
                er0 = fmaf(v0, ar0, fmaf(v1, ar1, er0));
                el1 = fmaf(v2, al0, fmaf(v3, al1, el1));
                er1 = fmaf(v2, ar0, fmaf(v3, ar1, er1));
                if (row < M)
                    *(__half2*)(C + (size_t)row * Nd + n0 + o) = __floats2half2_rn(v0, v1);
                if (row + 8 < M)
                    *(__half2*)(C + (size_t)(row + 8) * Nd + n0 + o) = __floats2half2_rn(v2, v3);
            }
#pragma unroll
            for (int off = 1; off <= 2; off <<= 1) {
                el0 += __shfl_xor_sync(0xFFFFFFFFu, el0, off);
                er0 += __shfl_xor_sync(0xFFFFFFFFu, er0, off);
                el1 += __shfl_xor_sync(0xFFFFFFFFu, el1, off);
                er1 += __shfl_xor_sync(0xFFFFFFFFu, er1, off);
            }
            if (tig == 0) {
                if (row < M) {
                    atomicAdd(&g_el[(bz * Nn + row) * H + hidx], el0);
                    atomicAdd(&g_er[(bz * Nn + row) * H + hidx], er0);
                }
                if (row + 8 < M) {
                    atomicAdd(&g_el[(bz * Nn + row + 8) * H + hidx], el1);
                    atomicAdd(&g_er[(bz * Nn + row + 8) * H + hidx], er1);
                }
            }
        }
    } else {
        if (tid < 64) {
            fsm[tid]      = bias[tid];
            fsm[64 + tid] = W2p[tid];
        }
        __syncthreads();
#pragma unroll
        for (int mt = 0; mt < 4; mt++) {
            int row = m0 + wm * 64 + mt * 16 + gid;
            float w0 = 0.f, w1 = 0.f;
#pragma unroll
            for (int nt = 0; nt < 4; nt++) {
                int o = wn * 32 + nt * 8 + 2 * tig;
                float b0 = fsm[o], b1v = fsm[o + 1];
                float w2a = fsm[64 + o], w2b = fsm[64 + o + 1];
                w0 = fmaf(tanhf(c[mt][nt][0] + b0), w2a,
                     fmaf(tanhf(c[mt][nt][1] + b1v), w2b, w0));
                w1 = fmaf(tanhf(c[mt][nt][2] + b0), w2a,
                     fmaf(tanhf(c[mt][nt][3] + b1v), w2b, w1));
            }
#pragma unroll
            for (int off = 1; off <= 2; off <<= 1) {
                w0 += __shfl_xor_sync(0xFFFFFFFFu, w0, off);
                w1 += __shfl_xor_sync(0xFFFFFFFFu, w1, off);
            }
            if (tig == 0) {
                if (row < M)     atomicAdd(&g_w[bz * Nn + row], w0);
                if (row + 8 < M) atomicAdd(&g_w[bz * Nn + row + 8], w1);
            }
        }
    }
}

// ---------------- CSR scan + scatter ----------------------------------------------
__global__ void k_scan1() {
    int chunk = blockIdx.x, r = blockIdx.y;
    int t = threadIdx.x;
    __shared__ int ws[8];
    int base = chunk * 1024 + t * 4;
    const int* cnt = g_cnt + r * Nn;
    int v[4];
#pragma unroll
    for (int j = 0; j < 4; j++) {
        int i = base + j;
        v[j] = (i < Nn) ? cnt[i] : 0;
    }
    int s = v[0] + v[1] + v[2] + v[3];
    int lane = t & 31, w = t >> 5;
    int x = s;
#pragma unroll
    for (int off = 1; off < 32; off <<= 1) {
        int y = __shfl_up_sync(0xFFFFFFFFu, x, off);
        if (lane >= off) x += y;
    }
    if (lane == 31) ws[w] = x;
    __syncthreads();
    if (t < 8) {
        int y = ws[t];
#pragma unroll
        for (int off = 1; off < 8; off <<= 1) {
            int z = __shfl_up_sync(0xFFu, y, off);
            if (t >= off) y += z;
        }
        ws[t] = y;
    }
    __syncthreads();
    int excl = x - s + (w > 0 ? ws[w - 1] : 0);
    int* rp = g_rowptr + r * (Nn + 1);
    int run = excl;
#pragma unroll
    for (int j = 0; j < 4; j++) {
        int i = base + j;
        if (i < Nn) rp[i] = run;
        run += v[j];
    }
    if (t == 255) g_bsum[r * NCHUNK + chunk] = excl + s;
}

// merged phase 2+3: warp-parallel prefix of chunk sums, offset-add + cursor write
__global__ void k_scan3() {
    int chunk = blockIdx.x, r = blockIdx.y;
    int t = threadIdx.x;
    __shared__ int s_off;
    if (t < 32) {
        int v = (t < chunk) ? g_bsum[r * NCHUNK + t] : 0;
#pragma unroll
        for (int off = 16; off > 0; off >>= 1)
            v += __shfl_down_sync(0xFFFFFFFFu, v, off);
        if (t == 0) s_off = v;
    }
    __syncthreads();
    int off = s_off;
    int* rp = g_rowptr + r * (Nn + 1);
#pragma unroll
    for (int j = 0; j < 4; j++) {
        int i = chunk * 1024 + t * 4 + j;
        if (i < Nn) {
            int val = rp[i] + off;
            rp[i] = val;
            g_cursor[r * Nn + i] = val;
        }
    }
    if (chunk == 0 && t == 0) rp[Nn] = E;
}

__global__ void k_scatter(const int* __restrict__ dstA) {
    int t = blockIdx.x * blockDim.x + threadIdx.x;
    if (t >= R * E) return;
    int r = t / E, e = t % E;
    int d = dstA[t];
    int p = atomicAdd(&g_cursor[r * Nn + d], 1);
    g_eid[(size_t)r * E + p] = e;
}

// ---------------- fused edge-softmax + aggregate (writes z16 only) ----------------
__global__ void __launch_bounds__(128) k_sagg(const int* __restrict__ srcA,
                                              const float* __restrict__ bias) {
    int n = blockIdx.x, r = blockIdx.y;
    int tid = threadIdx.x;
    int s0 = g_rowptr[r * (Nn + 1) + n];
    int s1 = g_rowptr[r * (Nn + 1) + n + 1];
    int deg = s1 - s0;

    __shared__ float s_attn[CAP * 8];
    __shared__ float s_m[4][8], s_s[4][8];
    __shared__ float s_M[8], s_I[8];

    const int* eid = g_eid + (size_t)r * E;
    const int* src = srcA + (size_t)r * E;
    const float* elb = g_el + (size_t)r * Nn * H;
    float* buf = (deg <= CAP) ? s_attn : (g_attn + ((size_t)r * E + s0) * H);

    int h = tid & 7, li0 = tid >> 3;
    float erv = g_er[((size_t)r * Nn + n) * H + h];
    float m = -3.4e38f, ssum = 0.f;
    for (int li = li0; li < deg; li += 16) {
        int e = eid[s0 + li];
        float v = elb[(size_t)src[e] * H + h] + erv;
        v = (v > 0.f) ? v : 0.2f * v;
        buf[li * 8 + h] = v;
        if (v > m) {
            ssum = ssum * expf(m - v) + 1.f;
            m = v;
        } else {
            ssum += expf(v - m);
        }
    }
    int lane = tid & 31, w = tid >> 5;
#pragma unroll
    for (int off = 8; off <= 16; off <<= 1) {
        float m2 = __shfl_xor_sync(0xFFFFFFFFu, m, off);
        float s2 = __shfl_xor_sync(0xFFFFFFFFu, ssum, off);
        float M = fmaxf(m, m2);
        ssum = ssum * expf(m - M) + s2 * expf(m2 - M);
        m = M;
    }
    if (lane < 8) { s_m[w][lane] = m; s_s[w][lane] = ssum; }
    __syncthreads();
    if (tid < 8) {
        float M = s_m[0][tid], S = s_s[0][tid];
#pragma unroll
        for (int ww = 1; ww < 4; ww++) {
            float m2 = s_m[ww][tid], s2 = s_s[ww][tid];
            float Mx = fmaxf(M, m2);
            S = S * expf(M - Mx) + s2 * expf(m2 - Mx);
            M = Mx;
        }
        s_M[tid] = M;
        s_I[tid] = 1.f / S;
    }
    __syncthreads();

    for (int idx = tid; idx < deg * 8; idx += 128)
        buf[idx] = expf(buf[idx] - s_M[idx & 7]) * s_I[idx & 7];
    __syncthreads();

    int col = tid * 4, hh = tid >> 4;
    const __half* hb = g_h16 + (size_t)r * Nn * D;
    float a0 = 0.f, a1 = 0.f, a2 = 0.f, a3 = 0.f;
    int li = 0;
    for (; li + 1 < deg; li += 2) {
        int e0 = eid[s0 + li], e1 = eid[s0 + li + 1];
        int sn0 = src[e0], sn1 = src[e1];
        float w0 = buf[li * 8 + hh];
        float w1 = buf[(li + 1) * 8 + hh];
        const __half2* q0 = (const __half2*)(hb + (size_t)sn0 * D + col);
        const __half2* q1 = (const __half2*)(hb + (size_t)sn1 * D + col);
        float2 u0 = __half22float2(q0[0]), u1 = __half22float2(q0[1]);
        float2 v0 = __half22float2(q1[0]), v1 = __half22float2(q1[1]);
        a0 = fmaf(w0, u0.x, a0); a1 = fmaf(w0, u0.y, a1);
        a2 = fmaf(w0, u1.x, a2); a3 = fmaf(w0, u1.y, a3);
        a0 = fmaf(w1, v0.x, a0); a1 = fmaf(w1, v0.y, a1);
        a2 = fmaf(w1, v1.x, a2); a3 = fmaf(w1, v1.y, a3);
    }
    if (li < deg) {
        int e = eid[s0 + li];
        int sn = src[e];
        float wv = buf[li * 8 + hh];
        const __half2* q = (const __half2*)(hb + (size_t)sn * D + col);
        float2 u0 = __half22float2(q[0]), u1 = __half22float2(q[1]);
        a0 = fmaf(wv, u0.x, a0); a1 = fmaf(wv, u0.y, a1);
        a2 = fmaf(wv, u1.x, a2); a3 = fmaf(wv, u1.y, a3);
    }
    float4 bv = *(const float4*)(bias + r * D + col);
    float4 o;
    o.x = fminf(fmaxf(a0 + bv.x, 0.f), 6.f);
    o.y = fminf(fmaxf(a1 + bv.y, 0.f), 6.f);
    o.z = fminf(fmaxf(a2 + bv.z, 0.f), 6.f);
    o.w = fminf(fmaxf(a3 + bv.w, 0.f), 6.f);
    *(float2*)(g_z16 + ((size_t)(r * Nn + n)) * D + col) = f4_to_h4(o);
}

// ---------------- deterministic mean over nodes -----------------------------------
__global__ void k_wreduce() {
    int r = blockIdx.x;
    __shared__ float sh[1024];
    float s = 0.f;
    for (int i = threadIdx.x; i < Nn; i += 1024) s += g_w[r * Nn + i];
    sh[threadIdx.x] = s;
    __syncthreads();
    for (int off = 512; off > 0; off >>= 1) {
        if (threadIdx.x < off) sh[threadIdx.x] += sh[threadIdx.x + off];
        __syncthreads();
    }
    if (threadIdx.x == 0) g_wmean[r] = sh[0] / (float)Nn;
}

// ---------------- out = sum_r beta[r] * z16[:, r, :] ------------------------------
__global__ void k_out(float* __restrict__ out) {
    int i = blockIdx.x * blockDim.x + threadIdx.x;
    if (i >= Nn * D / 4) return;
    float w0 = g_wmean[0], w1 = g_wmean[1], w2 = g_wmean[2];
    float mx = fmaxf(w0, fmaxf(w1, w2));
    float e0 = expf(w0 - mx), e1 = expf(w1 - mx), e2 = expf(w2 - mx);
    float inv = 1.f / (e0 + e1 + e2);
    float b0 = e0 * inv, b1 = e1 * inv, b2 = e2 * inv;
    H4 u0, u1, u2;
    u0.f2 = ((const float2*)g_z16)[i];
    u1.f2 = ((const float2*)(g_z16 + (size_t)Nn * D))[i];
    u2.f2 = ((const float2*)(g_z16 + (size_t)2 * Nn * D))[i];
    float2 p00 = __half22float2(u0.h2[0]), p01 = __half22float2(u0.h2[1]);
    float2 p10 = __half22float2(u1.h2[0]), p11 = __half22float2(u1.h2[1]);
    float2 p20 = __half22float2(u2.h2[0]), p21 = __half22float2(u2.h2[1]);
    float4 o;
    o.x = b0 * p00.x + b1 * p10.x + b2 * p20.x;
    o.y = b0 * p00.y + b1 * p10.y + b2 * p20.y;
    o.z = b0 * p01.x + b1 * p11.x + b2 * p21.x;
    o.w = b0 * p01.y + b1 * p11.y + b2 * p21.y;
    ((float4*)out)[i] = o;
}

// ---------------- host ------------------------------------------------------------
extern "C" void kernel_launch(void* const* d_in, const int* in_sizes, int n_in,
                              void* d_out, int out_size) {
    const float* feats = (const float*)d_in[0];
    const int*   src   = (const int*)d_in[1];
    const int*   dst   = (const int*)d_in[2];
    const float* W     = (const float*)d_in[3];
    const float* al    = (const float*)d_in[4];
    const float* ar    = (const float*)d_in[5];
    const float* bias  = (const float*)d_in[6];
    const float* W1    = (const float*)d_in[7];
    const float* b1    = (const float*)d_in[8];
    const float* W2    = (const float*)d_in[9];
    float* out = (float*)d_out;

    __half *aptr, *bptr, *w1ptr, *hptr, *z16ptr;
    cudaGetSymbolAddress((void**)&aptr, g_a16);
    cudaGetSymbolAddress((void**)&bptr, g_b16);
    cudaGetSymbolAddress((void**)&w1ptr, g_w116);
    cudaGetSymbolAddress((void**)&hptr, g_h16);
    cudaGetSymbolAddress((void**)&z16ptr, g_z16);

    cudaFuncSetAttribute(k_gemm_tc, cudaFuncAttributeMaxDynamicSharedMemorySize,
                         GSMEM);

    k_init<<<(NA4 + 255) / 256, 256>>>(feats, W, W1);

    // GEMM1 + overlapped histogram (blockIdx.y == 8)
    k_gemm_tc<<<dim3((Nn + GBM - 1) / GBM, D / GBN + 1, R), 128, GSMEM>>>(
        aptr, bptr, hptr, al, ar, (const float*)0, (const float*)0, dst,
        Nn, F, D, (size_t)Nn * F, (size_t)F * D, (size_t)Nn * D, 0);

    k_scan1<<<dim3(NCHUNK, R), 256>>>();
    k_scan3<<<dim3(NCHUNK, R), 256>>>();
    k_scatter<<<(R * E + 255) / 256, 256>>>(dst);

    k_sagg<<<dim3(Nn, R), 128>>>(src, bias);

    // GEMM2: w += tanh(z16 @ w116 + b1) @ W2
    k_gemm_tc<<<dim3((Nn + GBM - 1) / GBM, 1, R), 128, GSMEM>>>(
        z16ptr, w1ptr, (__half*)0, (const float*)0, (const float*)0, b1, W2,
        (const int*)0, Nn, D, O, (size_t)Nn * D, 0, 0, 1);

    k_wreduce<<<R, 1024>>>();
    k_out<<<(Nn * D / 4 + 255) / 256, 256>>>(out);
}

// round 17
// speedup vs baseline: 1.4300x; 1.0107x over previous
#include <cuda_runtime.h>
#include <cuda_fp16.h>
#include <stdint.h>
#include <math.h>

#define R  3
#define Nn 20000
#define E  320000
#define F  256
#define H  8
#define O  64
#define D  512
#define NCHUNK 20
#define CAP 96

// ---------------- scratch (static device globals; no allocations) ----------------
__device__ __half g_a16[(size_t)R * Nn * F];
__device__ __half g_b16[(size_t)R * F * D];
__device__ __half g_w116[D * O];
__device__ __half g_h16[(size_t)R * Nn * D];
__device__ __half g_z16[(size_t)R * Nn * D];
__device__ float g_el[R * Nn * H];
__device__ float g_er[R * Nn * H];
__device__ int   g_cnt[R * Nn];
__device__ int   g_rowptr[R * (Nn + 1)];
__device__ int   g_cursor[R * Nn];
__device__ int   g_bsum[R * NCHUNK];
__device__ int   g_eid[(size_t)R * E];
__device__ float g_attn[(size_t)R * E * H];     // fallback for deg > CAP
__device__ float g_w[R * Nn];
__device__ float g_wmean[R];

union H4 {
    float2 f2;
    __half2 h2[2];
};
__device__ __forceinline__ float2 f4_to_h4(float4 v) {
    H4 u;
    u.h2[0] = __floats2half2_rn(v.x, v.y);
    u.h2[1] = __floats2half2_rn(v.z, v.w);
    return u.f2;
}

// ---------------- init: zero accumulators + fp32->fp16 conversion -----------------
#define NA4 (R * Nn * F / 4)
#define NB4 (R * F * D / 4)
#define NW4 (D * O / 4)
__global__ void k_init(const float* __restrict__ feats, const float* __restrict__ W,
                       const float* __restrict__ W1) {
    int i = blockIdx.x * blockDim.x + threadIdx.x;
    if (i < NA4)
        ((float2*)g_a16)[i] = f4_to_h4(((const float4*)feats)[i]);
    if (i < NB4)
        ((float2*)g_b16)[i] = f4_to_h4(((const float4*)W)[i]);
    if (i < NW4)
        ((float2*)g_w116)[i] = f4_to_h4(((const float4*)W1)[i]);
    if (i < R * Nn) g_w[i] = 0.f;
    if (i < R * Nn * H) { g_el[i] = 0.f; g_er[i] = 0.f; }
}

// cnt zero — side stream, ahead of hist
__global__ void k_zcnt() {
    int i = blockIdx.x * blockDim.x + threadIdx.x;
    if (i < R * Nn) g_cnt[i] = 0;
}

// ================= FP16 tensor-core GEMM: 3-stage cp.async ring ===================
#define GBM 128
#define GBN 64
#define GBK 32
#define AST2 40
#define BST2 72
#define ASZ2 (GBM * AST2)
#define BSZ2 (GBK * BST2)
#define STAGEB ((ASZ2 + BSZ2) * 2)
#define GSMEM (3 * STAGEB)

__device__ __forceinline__ void cpa16(unsigned dst, const void* src, int bytes) {
    asm volatile("cp.async.ca.shared.global [%0], [%1], 16, %2;\n"
                 :: "r"(dst), "l"(src), "r"(bytes));
}
__device__ __forceinline__ void cpa_commit() {
    asm volatile("cp.async.commit_group;\n");
}
__device__ __forceinline__ void cpa_wait0() {
    asm volatile("cp.async.wait_group 0;\n" ::: "memory");
}
__device__ __forceinline__ void cpa_wait1() {
    asm volatile("cp.async.wait_group 1;\n" ::: "memory");
}
__device__ __forceinline__ void ldsm4(unsigned* r, unsigned addr) {
    asm volatile("ldmatrix.sync.aligned.m8n8.x4.shared.b16 {%0,%1,%2,%3}, [%4];"
                 : "=r"(r[0]), "=r"(r[1]), "=r"(r[2]), "=r"(r[3]) : "r"(addr));
}
__device__ __forceinline__ void ldsm4t(unsigned* r, unsigned addr) {
    asm volatile("ldmatrix.sync.aligned.m8n8.x4.trans.shared.b16 {%0,%1,%2,%3}, [%4];"
                 : "=r"(r[0]), "=r"(r[1]), "=r"(r[2]), "=r"(r[3]) : "r"(addr));
}

__global__ void __launch_bounds__(128, 3) k_gemm_tc(
    const __half* __restrict__ A0, const __half* __restrict__ B0,
    __half* __restrict__ C16,
    const float* __restrict__ alp, const float* __restrict__ arp,
    const float* __restrict__ bias, const float* __restrict__ W2p,
    int M, int K, int Nd,
    size_t sA, size_t sB, size_t sC, int mode)
{
    const int bz = blockIdx.z;
    const int tid = threadIdx.x;

    extern __shared__ __half hsm[];
    float* fsm = (float*)hsm;

    const __half* A = A0 + (size_t)bz * sA;
    const __half* B = B0 + (size_t)bz * sB;

    const int lane = tid & 31, wid = tid >> 5;
    const int gid  = lane >> 2, tig = lane & 3;
    const int wm   = wid >> 1, wn = wid & 1;
    const int m0   = blockIdx.x * GBM, n0 = blockIdx.y * GBN;

    const unsigned uS0 = (unsigned)__cvta_generic_to_shared(hsm);

    int aRow[4], aCh[4], aByte[4], aOK[4];
#pragma unroll
    for (int j = 0; j < 4; j++) {
        int idx = tid + j * 128;
        aRow[j] = idx >> 2;
        aCh[j]  = (idx & 3) * 8;
        int gr = m0 + aRow[j];
        aOK[j] = (gr < M) ? 16 : 0;
        aByte[j] = (aRow[j] * AST2 + aCh[j]) * 2;
    }
    int bRow[2], bCh[2], bByte[2];
#pragma unroll
    for (int j = 0; j < 2; j++) {
        int idx = tid + j * 128;
        bRow[j] = idx >> 3;
        bCh[j]  = (idx & 7) * 8;
        bByte[j] = (bRow[j] * BST2 + bCh[j]) * 2;
    }

    const int aLRow = lane & 15, aLSel = lane >> 4;
    const int bLRow = lane & 15, bLSel = lane >> 4;

    float c[4][4][4];
#pragma unroll
    for (int i = 0; i < 4; i++)
#pragma unroll
        for (int j = 0; j < 4; j++) {
            c[i][j][0] = 0.f; c[i][j][1] = 0.f;
            c[i][j][2] = 0.f; c[i][j][3] = 0.f;
        }

    const int T = K / GBK;

#pragma unroll
    for (int st = 0; st < 2; st++) {
        if (st < T) {
            unsigned uAs = uS0 + st * STAGEB;
            unsigned uBs = uAs + ASZ2 * 2;
            int k0 = st * GBK;
#pragma unroll
            for (int j = 0; j < 4; j++) {
                int gr = m0 + aRow[j];
                int grc = (gr < M) ? gr : 0;
                cpa16(uAs + aByte[j], A + (size_t)grc * K + k0 + aCh[j], aOK[j]);
            }
#pragma unroll
            for (int j = 0; j < 2; j++)
                cpa16(uBs + bByte[j], B + (size_t)(k0 + bRow[j]) * Nd + n0 + bCh[j], 16);
            cpa_commit();
        }
    }

    for (int it = 0; it < T; it++) {
        if (it + 1 < T) cpa_wait1(); else cpa_wait0();
        __syncthreads();

        if (it + 2 < T) {
            int s2 = (it + 2) % 3;
            unsigned uAs = uS0 + s2 * STAGEB;
            unsigned uBs = uAs + ASZ2 * 2;
            int k0 = (it + 2) * GBK;
#pragma unroll
            for (int j = 0; j < 4; j++) {
                int gr = m0 + aRow[j];
                int grc = (gr < M) ? gr : 0;
                cpa16(uAs + aByte[j], A + (size_t)grc * K + k0 + aCh[j], aOK[j]);
            }
#pragma unroll
            for (int j = 0; j < 2; j++)
                cpa16(uBs + bByte[j], B + (size_t)(k0 + bRow[j]) * Nd + n0 + bCh[j], 16);
            cpa_commit();
        }

        int s = it % 3;
        unsigned uAc = uS0 + s * STAGEB;
        unsigned uBc = uAc + ASZ2 * 2;
#pragma unroll
        for (int kg = 0; kg < 2; kg++) {
            unsigned a[4][4], b[2][4];
#pragma unroll
            for (int mt = 0; mt < 4; mt++) {
                int row = wm * 64 + mt * 16 + aLRow;
                int ch  = kg * 16 + aLSel * 8;
                ldsm4(a[mt], uAc + (unsigned)(row * AST2 + ch) * 2u);
            }
#pragma unroll
            for (int nt2 = 0; nt2 < 2; nt2++) {
                int krow = kg * 16 + bLRow;
                int ncol = wn * 32 + nt2 * 16 + bLSel * 8;
                ldsm4t(b[nt2], uBc + (unsigned)(krow * BST2 + ncol) * 2u);
            }
#pragma unroll
            for (int mt = 0; mt < 4; mt++) {
#pragma unroll
                for (int nt = 0; nt < 4; nt++) {
                    unsigned bb0 = b[nt >> 1][(nt & 1) * 2];
                    unsigned bb1 = b[nt >> 1][(nt & 1) * 2 + 1];
                    asm volatile(
                        "mma.sync.aligned.m16n8k16.row.col.f32.f16.f16.f32 "
                        "{%0,%1,%2,%3}, {%4,%5,%6,%7}, {%8,%9}, {%0,%1,%2,%3};"
                        : "+f"(c[mt][nt][0]), "+f"(c[mt][nt][1]),
                          "+f"(c[mt][nt][2]), "+f"(c[mt][nt][3])
                        : "r"(a[mt][0]), "r"(a[mt][1]), "r"(a[mt][2]), "r"(a[mt][3]),
                          "r"(bb0), "r"(bb1));
                }
            }
        }
    }
    __syncthreads();   // epilogue fsm aliases stage 0

    if (mode == 0) {
        __half* C = C16 + (size_t)bz * sC;
        if (tid < 64) {
            fsm[tid]      = alp[bz * D + n0 + tid];
            fsm[64 + tid] = arp[bz * D + n0 + tid];
        }
        __syncthreads();
        const int hidx = blockIdx.y;
#pragma unroll
        for (int mt = 0; mt < 4; mt++) {
            int row = m0 + wm * 64 + mt * 16 + gid;
            float el0 = 0.f, er0 = 0.f, el1 = 0.f, er1 = 0.f;
#pragma unroll
            for (int nt = 0; nt < 4; nt++) {
                int o = wn * 32 + nt * 8 + 2 * tig;
                float al0 = fsm[o], al1 = fsm[o + 1];
                float ar0 = fsm[64 + o], ar1 = fsm[64 + o + 1];
                float v0 = c[mt][nt][0], v1 = c[mt][nt][1];
                float v2 = c[mt][nt][2], v3 = c[mt][nt][3];
                el0 = fmaf(v0, al0, fmaf(v1, al1, el0));
                er0 = fmaf(v0, ar0, fmaf(v1, ar1, er0));
                el1 = fmaf(v2, al0, fmaf(v3, al1, el1));
                er1 = fmaf(v2, ar0, fmaf(v3, ar1, er1));
                if (row < M)
                    *(__half2*)(C + (size_t)row * Nd + n0 + o) = __floats2half2_rn(v0, v1);
                if (row + 8 < M)
                    *(__half2*)(C + (size_t)(row + 8) * Nd + n0 + o) = __floats2half2_rn(v2, v3);
            }
#pragma unroll
            for (int off = 1; off <= 2; off <<= 1) {
                el0 += __shfl_xor_sync(0xFFFFFFFFu, el0, off);
                er0 += __shfl_xor_sync(0xFFFFFFFFu, er0, off);
                el1 += __shfl_xor_sync(0xFFFFFFFFu, el1, off);
                er1 += __shfl_xor_sync(0xFFFFFFFFu, er1, off);
            }
            if (tig == 0) {
                if (row < M) {
                    atomicAdd(&g_el[(bz * Nn + row) * H + hidx], el0);
                    atomicAdd(&g_er[(bz * Nn + row) * H + hidx], er0);
                }
                if (row + 8 < M) {
                    atomicAdd(&g_el[(bz * Nn + row + 8) * H + hidx], el1);
                    atomicAdd(&g_er[(bz * Nn + row + 8) * H + hidx], er1);
                }
            }
        }
    } else {
        if (tid < 64) {
            fsm[tid]      = bias[tid];
            fsm[64 + tid] = W2p[tid];
        }
        __syncthreads();
#pragma unroll
        for (int mt = 0; mt < 4; mt++) {
            int row = m0 + wm * 64 + mt * 16 + gid;
            float w0 = 0.f, w1 = 0.f;
#pragma unroll
            for (int nt = 0; nt < 4; nt++) {
                int o = wn * 32 + nt * 8 + 2 * tig;
                float b0 = fsm[o], b1v = fsm[o + 1];
                float w2a = fsm[64 + o], w2b = fsm[64 + o + 1];
                w0 = fmaf(tanhf(c[mt][nt][0] + b0), w2a,
                     fmaf(tanhf(c[mt][nt][1] + b1v), w2b, w0));
                w1 = fmaf(tanhf(c[mt][nt][2] + b0), w2a,
                     fmaf(tanhf(c[mt][nt][3] + b1v), w2b, w1));
            }
#pragma unroll
            for (int off = 1; off <= 2; off <<= 1) {
                w0 += __shfl_xor_sync(0xFFFFFFFFu, w0, off);
                w1 += __shfl_xor_sync(0xFFFFFFFFu, w1, off);
            }
            if (tig == 0) {
                if (row < M)     atomicAdd(&g_w[bz * Nn + row], w0);
                if (row + 8 < M) atomicAdd(&g_w[bz * Nn + row + 8], w1);
            }
        }
    }
}

// ---------------- CSR build (side stream) -----------------------------------------
__global__ void k_hist(const int* __restrict__ dstA) {
    int t = blockIdx.x * blockDim.x + threadIdx.x;
    if (t >= R * E) return;
    int r = t / E;
    atomicAdd(&g_cnt[r * Nn + dstA[t]], 1);
}

__global__ void k_scan1() {
    int chunk = blockIdx.x, r = blockIdx.y;
    int t = threadIdx.x;
    __shared__ int ws[8];
    int base = chunk * 1024 + t * 4;
    const int* cnt = g_cnt + r * Nn;
    int v[4];
#pragma unroll
    for (int j = 0; j < 4; j++) {
        int i = base + j;
        v[j] = (i < Nn) ? cnt[i] : 0;
    }
    int s = v[0] + v[1] + v[2] + v[3];
    int lane = t & 31, w = t >> 5;
    int x = s;
#pragma unroll
    for (int off = 1; off < 32; off <<= 1) {
        int y = __shfl_up_sync(0xFFFFFFFFu, x, off);
        if (lane >= off) x += y;
    }
    if (lane == 31) ws[w] = x;
    __syncthreads();
    if (t < 8) {
        int y = ws[t];
#pragma unroll
        for (int off = 1; off < 8; off <<= 1) {
            int z = __shfl_up_sync(0xFFu, y, off);
            if (t >= off) y += z;
        }
        ws[t] = y;
    }
    __syncthreads();
    int excl = x - s + (w > 0 ? ws[w - 1] : 0);
    int* rp = g_rowptr + r * (Nn + 1);
    int run = excl;
#pragma unroll
    for (int j = 0; j < 4; j++) {
        int i = base + j;
        if (i < Nn) rp[i] = run;
        run += v[j];
    }
    if (t == 255) g_bsum[r * NCHUNK + chunk] = excl + s;
}

__global__ void k_scan3() {
    int chunk = blockIdx.x, r = blockIdx.y;
    int t = threadIdx.x;
    __shared__ int s_off;
    if (t < 32) {
        int v = (t < chunk) ? g_bsum[r * NCHUNK + t] : 0;
#pragma unroll
        for (int off = 16; off > 0; off >>= 1)
            v += __shfl_down_sync(0xFFFFFFFFu, v, off);
        if (t == 0) s_off = v;
    }
    __syncthreads();
    int off = s_off;
    int* rp = g_rowptr + r * (Nn + 1);
#pragma unroll
    for (int j = 0; j < 4; j++) {
        int i = chunk * 1024 + t * 4 + j;
        if (i < Nn) {
            int val = rp[i] + off;
            rp[i] = val;
            g_cursor[r * Nn + i] = val;
        }
    }
    if (chunk == 0 && t == 0) rp[Nn] = E;
}

__global__ void k_scatter(const int* __restrict__ dstA) {
    int t = blockIdx.x * blockDim.x + threadIdx.x;
    if (t >= R * E) return;
    int r = t / E, e = t % E;
    int d = dstA[t];
    int p = atomicAdd(&g_cursor[r * Nn + d], 1);
    g_eid[(size_t)r * E + p] = e;
}

// ---------------- fused edge-softmax + aggregate (writes z16 only) ----------------
__global__ void __launch_bounds__(128) k_sagg(const int* __restrict__ srcA,
                                              const float* __restrict__ bias) {
    int n = blockIdx.x, r = blockIdx.y;
    int tid = threadIdx.x;
    int s0 = g_rowptr[r * (Nn + 1) + n];
    int s1 = g_rowptr[r * (Nn + 1) + n + 1];
    int deg = s1 - s0;

    __shared__ float s_attn[CAP * 8];
    __shared__ float s_m[4][8], s_s[4][8];
    __shared__ float s_M[8], s_I[8];

    const int* eid = g_eid + (size_t)r * E;
    const int* src = srcA + (size_t)r * E;
    const float* elb = g_el + (size_t)r * Nn * H;
    float* buf = (deg <= CAP) ? s_attn : (g_attn + ((size_t)r * E + s0) * H);

    int h = tid & 7, li0 = tid >> 3;
    float erv = g_er[((size_t)r * Nn + n) * H + h];
    float m = -3.4e38f, ssum = 0.f;
    for (int li = li0; li < deg; li += 16) {
        int e = eid[s0 + li];
        float v = elb[(size_t)src[e] * H + h] + erv;
        v = (v > 0.f) ? v : 0.2f * v;
        buf[li * 8 + h] = v;
        if (v > m) {
            ssum = ssum * expf(m - v) + 1.f;
            m = v;
        } else {
            ssum += expf(v - m);
        }
    }
    int lane = tid & 31, w = tid >> 5;
#pragma unroll
    for (int off = 8; off <= 16; off <<= 1) {
        float m2 = __shfl_xor_sync(0xFFFFFFFFu, m, off);
        float s2 = __shfl_xor_sync(0xFFFFFFFFu, ssum, off);
        float M = fmaxf(m, m2);
        ssum = ssum * expf(m - M) + s2 * expf(m2 - M);
        m = M;
    }
    if (lane < 8) { s_m[w][lane] = m; s_s[w][lane] = ssum; }
    __syncthreads();
    if (tid < 8) {
        float M = s_m[0][tid], S = s_s[0][tid];
#pragma unroll
        for (int ww = 1; ww < 4; ww++) {
            float m2 = s_m[ww][tid], s2 = s_s[ww][tid];
            float Mx = fmaxf(M, m2);
            S = S * expf(M - Mx) + s2 * expf(m2 - Mx);
            M = Mx;
        }
        s_M[tid] = M;
        s_I[tid] = 1.f / S;
    }
    __syncthreads();

    for (int idx = tid; idx < deg * 8; idx += 128)
        buf[idx] = expf(buf[idx] - s_M[idx & 7]) * s_I[idx & 7];
    __syncthreads();

    int col = tid * 4, hh = tid >> 4;
    const __half* hb = g_h16 + (size_t)r * Nn * D;
    float a0 = 0.f, a1 = 0.f, a2 = 0.f, a3 = 0.f;
    int li = 0;
    for (; li + 1 < deg; li += 2) {
        int e0 = eid[s0 + li], e1 = eid[s0 + li + 1];
        int sn0 = src[e0], sn1 = src[e1];
        float w0 = buf[li * 8 + hh];
        float w1 = buf[(li + 1) * 8 + hh];
        const __half2* q0 = (const __half2*)(hb + (size_t)sn0 * D + col);
        const __half2* q1 = (const __half2*)(hb + (size_t)sn1 * D + col);
        float2 u0 = __half22float2(q0[0]), u1 = __half22float2(q0[1]);
        float2 v0 = __half22float2(q1[0]), v1 = __half22float2(q1[1]);
        a0 = fmaf(w0, u0.x, a0); a1 = fmaf(w0, u0.y, a1);
        a2 = fmaf(w0, u1.x, a2); a3 = fmaf(w0, u1.y, a3);
        a0 = fmaf(w1, v0.x, a0); a1 = fmaf(w1, v0.y, a1);
        a2 = fmaf(w1, v1.x, a2); a3 = fmaf(w1, v1.y, a3);
    }
    if (li < deg) {
        int e = eid[s0 + li];
        int sn = src[e];
        float wv = buf[li * 8 + hh];
        const __half2* q = (const __half2*)(hb + (size_t)sn * D + col);
        float2 u0 = __half22float2(q[0]), u1 = __half22float2(q[1]);
        a0 = fmaf(wv, u0.x, a0); a1 = fmaf(wv, u0.y, a1);
        a2 = fmaf(wv, u1.x, a2); a3 = fmaf(wv, u1.y, a3);
    }
    float4 bv = *(const float4*)(bias + r * D + col);
    float4 o;
    o.x = fminf(fmaxf(a0 + bv.x, 0.f), 6.f);
    o.y = fminf(fmaxf(a1 + bv.y, 0.f), 6.f);
    o.z = fminf(fmaxf(a2 + bv.z, 0.f), 6.f);
    o.w = fminf(fmaxf(a3 + bv.w, 0.f), 6.f);
    *(float2*)(g_z16 + ((size_t)(r * Nn + n)) * D + col) = f4_to_h4(o);
}

// ---------------- deterministic mean over nodes -----------------------------------
__global__ void k_wreduce() {
    int r = blockIdx.x;
    __shared__ float sh[1024];
    float s = 0.f;
    for (int i = threadIdx.x; i < Nn; i += 1024) s += g_w[r * Nn + i];
    sh[threadIdx.x] = s;
    __syncthreads();
    for (int off = 512; off > 0; off >>= 1) {
        if (threadIdx.x < off) sh[threadIdx.x] += sh[threadIdx.x + off];
        __syncthreads();
    }
    if (threadIdx.x == 0) g_wmean[r] = sh[0] / (float)Nn;
}

// ---------------- out = sum_r beta[r] * z16[:, r, :] ------------------------------
__global__ void k_out(float* __restrict__ out) {
    int i = blockIdx.x * blockDim.x + threadIdx.x;
    if (i >= Nn * D / 4) return;
    float w0 = g_wmean[0], w1 = g_wmean[1], w2 = g_wmean[2];
    float mx = fmaxf(w0, fmaxf(w1, w2));
    float e0 = expf(w0 - mx), e1 = expf(w1 - mx), e2 = expf(w2 - mx);
    float inv = 1.f / (e0 + e1 + e2);
    float b0 = e0 * inv, b1 = e1 * inv, b2 = e2 * inv;
    H4 u0, u1, u2;
    u0.f2 = ((const float2*)g_z16)[i];
    u1.f2 = ((const float2*)(g_z16 + (size_t)Nn * D))[i];
    u2.f2 = ((const float2*)(g_z16 + (size_t)2 * Nn * D))[i];
    float2 p00 = __half22float2(u0.h2[0]), p01 = __half22float2(u0.h2[1]);
    float2 p10 = __half22float2(u1.h2[0]), p11 = __half22float2(u1.h2[1]);
    float2 p20 = __half22float2(u2.h2[0]), p21 = __half22float2(u2.h2[1]);
    float4 o;
    o.x = b0 * p00.x + b1 * p10.x + b2 * p20.x;
    o.y = b0 * p00.y + b1 * p10.y + b2 * p20.y;
    o.z = b0 * p01.x + b1 * p11.x + b2 * p21.x;
    o.w = b0 * p01.y + b1 * p11.y + b2 * p21.y;
    ((float4*)out)[i] = o;
}

// ---------------- host ------------------------------------------------------------
extern "C" void kernel_launch(void* const* d_in, const int* in_sizes, int n_in,
                              void* d_out, int out_size) {
    const float* feats = (const float*)d_in[0];
    const int*   src   = (const int*)d_in[1];
    const int*   dst   = (const int*)d_in[2];
    const float* W     = (const float*)d_in[3];
    const float* al    = (const float*)d_in[4];
    const float* ar    = (const float*)d_in[5];
    const float* bias  = (const float*)d_in[6];
    const float* W1    = (const float*)d_in[7];
    const float* b1    = (const float*)d_in[8];
    const float* W2    = (const float*)d_in[9];
    float* out = (float*)d_out;

    __half *aptr, *bptr, *w1ptr, *hptr, *z16ptr;
    cudaGetSymbolAddress((void**)&aptr, g_a16);
    cudaGetSymbolAddress((void**)&bptr, g_b16);
    cudaGetSymbolAddress((void**)&w1ptr, g_w116);
    cudaGetSymbolAddress((void**)&hptr, g_h16);
    cudaGetSymbolAddress((void**)&z16ptr, g_z16);

    // one-time side stream + fork/join events (created on first, non-captured call)
    static cudaStream_t s1 = nullptr;
    static cudaEvent_t evFork = nullptr, evJoin = nullptr;
    static bool attrDone = false;
    if (!s1) {
        cudaStreamCreateWithFlags(&s1, cudaStreamNonBlocking);
        cudaEventCreateWithFlags(&evFork, cudaEventDisableTiming);
        cudaEventCreateWithFlags(&evJoin, cudaEventDisableTiming);
    }
    if (!attrDone) {
        cudaFuncSetAttribute(k_gemm_tc, cudaFuncAttributeMaxDynamicSharedMemorySize,
                             GSMEM);
        attrDone = true;
    }

    cudaStream_t s0 = 0;   // legacy default stream (the captured stream)

    // ---- fork: CSR chain on s1, projection on s0 ----
    cudaEventRecord(evFork, s0);
    cudaStreamWaitEvent(s1, evFork, 0);

    // s1: CSR build (depends only on dst)
    k_zcnt<<<(R * Nn + 255) / 256, 256, 0, s1>>>();
    k_hist<<<(R * E + 255) / 256, 256, 0, s1>>>(dst);
    k_scan1<<<dim3(NCHUNK, R), 256, 0, s1>>>();
    k_scan3<<<dim3(NCHUNK, R), 256, 0, s1>>>();
    k_scatter<<<(R * E + 255) / 256, 256, 0, s1>>>(dst);
    cudaEventRecord(evJoin, s1);

    // s0: fp16 conversion + GEMM1 (+ fused el/er)
    k_init<<<(NA4 + 255) / 256, 256, 0, s0>>>(feats, W, W1);
    k_gemm_tc<<<dim3((Nn + GBM - 1) / GBM, D / GBN, R), 128, GSMEM, s0>>>(
        aptr, bptr, hptr, al, ar, (const float*)0, (const float*)0,
        Nn, F, D, (size_t)Nn * F, (size_t)F * D, (size_t)Nn * D, 0);

    // ---- join, then the dependent tail ----
    cudaStreamWaitEvent(s0, evJoin, 0);

    k_sagg<<<dim3(Nn, R), 128, 0, s0>>>(src, bias);

    k_gemm_tc<<<dim3((Nn + GBM - 1) / GBM, 1, R), 128, GSMEM, s0>>>(
        z16ptr, w1ptr, (__half*)0, (const float*)0, (const float*)0, b1, W2,
        Nn, D, O, (size_t)Nn * D, 0, 0, 1);

    k_wreduce<<<R, 1024, 0, s0>>>();
    k_out<<<(Nn * D / 4 + 255) / 256, 256, 0, s0>>>(out);
}